// round 10
// baseline (speedup 1.0000x reference)
#include <cuda_runtime.h>
#include <cuda_bf16.h>

// ---------------------------------------------------------------------------
// AdaptiveSpectralBlock: B=2, C=512, D=1024, K=64, FB=513
//   spectrum = tokens @ A   (A precomputed from DFT x P, stored transposed)
//   fr = Re(spectrum*gw + spectrum*mask*lw)
//   score[k](t=fr) = b2 + sum_j t^j * Acoef[j][k]   (exact-GELU Taylor moments)
//   weights = softmax_k(score); pooled = (weights*fr) @ E; out = LN(tokens+pooled)
// ---------------------------------------------------------------------------

#define Dm 1024
#define Kk 64
#define FB 513
#define NROWS 1024            // B*C
#define RPB 4                 // rows per k_main block
#define NJ 11                 // poly degree 0..10
#define NSPLIT 8              // j-splits in E@W1 GEMM
#define FSPLIT 4              // f-splits in buildA DFT

typedef unsigned long long ull;

// scratch (allocation-free rule: __device__ globals)
__device__ float g_ATp[FSPLIT][128 * Dm];       // buildA partials per f-quarter
__device__ float g_AT[128 * Dm];                // [col][d]; col 0..63 re, 64..127 im
__device__ float g_Mpart2[NSPLIT * Kk * Dm];    // partial m[k][d] per j-split
__device__ float g_Acoef[NJ * Kk];              // [j][k]

// gelu(y) = 0.5y + (1/sqrt(2pi)) (y^2 - y^4/6 + y^6/40 - y^8/336 + y^10/3456)
__constant__ float c_cp[NJ] = {
    0.0f, 0.5f,
    0.39894228040143270f, 0.0f,
   -0.06649038006690545f, 0.0f,
    0.00997355701003582f, 0.0f,
   -0.00118732821548045f, 0.0f,
    1.1543006956058354e-4f
};
__constant__ float c_binom[NJ][NJ] = {
    {1,0,0,0,0,0,0,0,0,0,0},
    {1,1,0,0,0,0,0,0,0,0,0},
    {1,2,1,0,0,0,0,0,0,0,0},
    {1,3,3,1,0,0,0,0,0,0,0},
    {1,4,6,4,1,0,0,0,0,0,0},
    {1,5,10,10,5,1,0,0,0,0,0},
    {1,6,15,20,15,6,1,0,0,0,0},
    {1,7,21,35,35,21,7,1,0,0,0},
    {1,8,28,56,70,56,28,8,1,0,0},
    {1,9,36,84,126,126,84,36,9,1,0},
    {1,10,45,120,210,252,210,120,45,10,1}
};

__device__ __forceinline__ void fma2(ull& acc, ull a, ull b) {
    asm("fma.rn.f32x2 %0, %1, %2, %0;" : "+l"(acc) : "l"(a), "l"(b));
}
__device__ __forceinline__ ull dup2(float v) {
    ull r;
    asm("mov.b64 %0, {%1, %1};" : "=l"(r) : "f"(v));
    return r;
}
__device__ __forceinline__ float2 unpack2(ull v) {
    float2 r;
    asm("mov.b64 {%0, %1}, %2;" : "=f"(r.x), "=f"(r.y) : "l"(v));
    return r;
}

// ---------------------------------------------------------------------------
// K_pre: fused precompute.
//   blocks [0,512):   buildA partial: d-group (b>>2)*8, f-quarter (b&3)
//   blocks [512,640): m = E @ W1 split-K GEMM partials
// ---------------------------------------------------------------------------
__global__ void __launch_bounds__(256) k_pre(const float* __restrict__ P,
                                             const float* __restrict__ E,
                                             const float* __restrict__ W1) {
    __shared__ __align__(16) char sm[40960];
    int t = threadIdx.x;

    if (blockIdx.x < 512) {
        // ---------------- buildA role (one f-quarter) ----------------
        float2* stw = (float2*)sm;                 // 8KB twiddles (cos, -sin)
        float*  sP  = (float*)(sm + 8192);         // 32KB P f-tile (128 f x 64 k)

        int h  = blockIdx.x & 3;                   // f-quarter
        int dg = blockIdx.x >> 2;                  // d-group 0..127
        int f0 = h << 7;

        #pragma unroll
        for (int i = 0; i < 4; ++i) {
            int idx = t + i * 256;
            float s, c;
            sincospif((float)idx * (2.0f / (float)Dm), &s, &c);
            stw[idx] = make_float2(c, -s);
        }
        const float4* P4 = (const float4*)P;
        #pragma unroll
        for (int i = 0; i < 8; ++i) {
            int lin4 = t + i * 256;                // 2048 float4 = 128 f x 16
            ((float4*)sP)[lin4] = P4[f0 * 16 + lin4];
        }
        __syncthreads();

        int k = t & 63, dq = t >> 6;
        int d0 = dg * 8;
        int da = d0 + dq, db = da + 4;
        ull accA = 0ull, accB = 0ull;              // (re, im) pairs
        int ia = (f0 * da) & (Dm - 1);
        int ib = (f0 * db) & (Dm - 1);

        #pragma unroll 4
        for (int ff = 0; ff < 128; ++ff) {
            ull wa = *(const ull*)&stw[ia];
            ull wb = *(const ull*)&stw[ib];
            ull pvd = dup2(sP[ff * 64 + k]);
            fma2(accA, wa, pvd);
            fma2(accB, wb, pvd);
            ia = (ia + da) & (Dm - 1);
            ib = (ib + db) & (Dm - 1);
        }
        float2 ab = unpack2(accA);
        float2 bb = unpack2(accB);
        float ara = ab.x, aia = ab.y, arb = bb.x, aib = bb.y;

        if (h == 3) {                              // Nyquist: cos=(-1)^d, sin=0
            float pn = P[512 * 64 + k];
            float sgn = (da & 1) ? -1.f : 1.f;
            ara = fmaf(sgn, pn, ara);
            arb = fmaf(sgn, pn, arb);
        }

        float* dst = g_ATp[h];
        dst[k * Dm + da]        = ara;
        dst[(64 + k) * Dm + da] = aia;
        dst[k * Dm + db]        = arb;
        dst[(64 + k) * Dm + db] = aib;
    } else {
        // ---------------- gemm role ----------------
        float* sE = (float*)sm;                    // 64x36 (9216B)
        float* sW = (float*)(sm + 9216);           // 32x64 (8192B)
        int bid = blockIdx.x - 512;
        int bd = bid & 15, bj = bid >> 4;
        int d0 = bd * 64, j0 = bj * 128;
        int tk = (t >> 4) * 4;
        int tc = t & 15;
        int td = tc * 4;

        ull acc[4][2];
        #pragma unroll
        for (int r = 0; r < 4; ++r) { acc[r][0] = 0ull; acc[r][1] = 0ull; }

        const float4* E4 = (const float4*)E;
        const float4* W14 = (const float4*)W1;

        for (int js = 0; js < 128; js += 32) {
            __syncthreads();
            #pragma unroll
            for (int i = 0; i < 2; ++i) {
                int lin4 = t + i * 256;
                int kr = lin4 >> 3, jc = lin4 & 7;
                float4 v = E4[kr * 256 + ((j0 + js) >> 2) + jc];
                *(float4*)&sE[kr * 36 + jc * 4] = v;
            }
            #pragma unroll
            for (int i = 0; i < 2; ++i) {
                int lin4 = t + i * 256;
                int jr = lin4 >> 4, dc = lin4 & 15;
                float4 v = W14[(j0 + js + jr) * 256 + (d0 >> 2) + dc];
                ((float4*)sW)[jr * 16 + dc] = v;
            }
            __syncthreads();
            #pragma unroll
            for (int jj = 0; jj < 32; ++jj) {
                ulonglong2 wp = ((const ulonglong2*)sW)[jj * 8 + tc];
                ull e0 = dup2(sE[(tk + 0) * 36 + jj]);
                ull e1 = dup2(sE[(tk + 1) * 36 + jj]);
                ull e2 = dup2(sE[(tk + 2) * 36 + jj]);
                ull e3 = dup2(sE[(tk + 3) * 36 + jj]);
                fma2(acc[0][0], e0, wp.x); fma2(acc[0][1], e0, wp.y);
                fma2(acc[1][0], e1, wp.x); fma2(acc[1][1], e1, wp.y);
                fma2(acc[2][0], e2, wp.x); fma2(acc[2][1], e2, wp.y);
                fma2(acc[3][0], e3, wp.x); fma2(acc[3][1], e3, wp.y);
            }
        }
        #pragma unroll
        for (int r = 0; r < 4; ++r) {
            ulonglong2 o; o.x = acc[r][0]; o.y = acc[r][1];
            *(ulonglong2*)&g_Mpart2[((bj << 6) + tk + r) * Dm + d0 + td] = o;
        }
    }
}

// ----------- K2: (a) moments Acoef[j][k] from m partials; (b) A combine
//   blocks [0,64):    powred role (one k each)
//   blocks [64,192):  combine g_AT = sum_h g_ATp[h]  (4096 floats each)
__global__ void __launch_bounds__(256) k_powred(const float* __restrict__ b1,
                                                const float* __restrict__ w2) {
    int t = threadIdx.x;
    if (blockIdx.x >= 64) {
        int cb = blockIdx.x - 64;                  // 0..127
        int base4 = cb * 1024;                     // float4 index base
        const float4* p0 = (const float4*)g_ATp[0];
        const float4* p1 = (const float4*)g_ATp[1];
        const float4* p2 = (const float4*)g_ATp[2];
        const float4* p3 = (const float4*)g_ATp[3];
        float4* o = (float4*)g_AT;
        #pragma unroll
        for (int i = 0; i < 4; ++i) {
            int idx = base4 + t + i * 256;
            float4 a = p0[idx], b = p1[idx], c = p2[idx], d = p3[idx];
            float4 s;
            s.x = (a.x + b.x) + (c.x + d.x);
            s.y = (a.y + b.y) + (c.y + d.y);
            s.z = (a.z + b.z) + (c.z + d.z);
            s.w = (a.w + b.w) + (c.w + d.w);
            o[idx] = s;
        }
        return;
    }

    __shared__ float red[8][NJ];
    int k = blockIdx.x;
    int d = t * 4;
    int w = t >> 5, lane = t & 31;

    float4 m4 = make_float4(0.f, 0.f, 0.f, 0.f);
    #pragma unroll
    for (int p = 0; p < NSPLIT; ++p) {
        float4 v = *(const float4*)&g_Mpart2[((p << 6) + k) * Dm + d];
        m4.x += v.x; m4.y += v.y; m4.z += v.z; m4.w += v.w;
    }
    float4 b4 = *(const float4*)&b1[d];
    float4 w4 = *(const float4*)&w2[d];

    float accj[NJ];
    #pragma unroll
    for (int j = 0; j < NJ; ++j) accj[j] = 0.f;

    float mlane[4] = {m4.x, m4.y, m4.z, m4.w};
    float blane[4] = {b4.x, b4.y, b4.z, b4.w};
    float wlane[4] = {w4.x, w4.y, w4.z, w4.w};
    #pragma unroll
    for (int q = 0; q < 4; ++q) {
        float bb = blane[q], ww = wlane[q], mm = mlane[q];
        float bp[NJ];
        bp[0] = 1.f;
        #pragma unroll
        for (int i = 1; i < NJ; ++i) bp[i] = bp[i - 1] * bb;
        float mp = 1.f;
        #pragma unroll
        for (int j = 0; j < NJ; ++j) {
            float gj = 0.f;
            #pragma unroll
            for (int p = 0; p < NJ; ++p) {
                if (p >= j) gj = fmaf(c_cp[p] * c_binom[p][j], bp[p - j], gj);
            }
            accj[j] = fmaf(ww * gj, mp, accj[j]);
            mp *= mm;
        }
    }
    #pragma unroll
    for (int j = 0; j < NJ; ++j) {
        float a = accj[j];
        #pragma unroll
        for (int off = 16; off; off >>= 1)
            a += __shfl_xor_sync(0xffffffffu, a, off);
        if (lane == 0) red[w][j] = a;
    }
    __syncthreads();
    if (t < NJ) {
        float s = 0.f;
        #pragma unroll
        for (int i = 0; i < 8; ++i) s += red[i][t];
        g_Acoef[t * Kk + k] = s;
    }
}

// ------------------------------------------------------- K3: fused main
// grid 256 blocks x 512 threads, 4 rows per block, 2 CTAs/SM.
__global__ void __launch_bounds__(512, 2) k_main(
    const float* __restrict__ tokens, const float* __restrict__ thr_p,
    const float* __restrict__ Gr, const float* __restrict__ Gi,
    const float* __restrict__ Lr, const float* __restrict__ Li,
    const float* __restrict__ E, const float* __restrict__ b2p,
    const float* __restrict__ gamma, const float* __restrict__ beta,
    float* __restrict__ out)
{
    __shared__ float xs[RPB * Dm];              // 16KB tokens
    __shared__ float sp2[2][RPB * 128];         // depth-half spectrum partials
    __shared__ float as2[Kk * RPB * 2];         // weight*fr dup pairs [k][r][2]
    __shared__ float ac[NJ * Kk];
    __shared__ float red1[RPB][16], red2[RPB][16];
    __shared__ float rmean[RPB], rrstd[RPB];

    int t = threadIdx.x;
    int row0 = blockIdx.x * RPB;
    int w = t >> 5, lane = t & 31;

    // ---- stage tokens + coefficients
    {
        const float4* tok4 = (const float4*)(tokens + row0 * Dm);
        float4* xs4 = (float4*)xs;
        #pragma unroll
        for (int i = 0; i < 2; ++i) xs4[t + i * 512] = tok4[t + i * 512];
        for (int i = t; i < NJ * Kk; i += 512) ac[i] = g_Acoef[i];
    }
    __syncthreads();

    // ---- spectrum (tokens @ A): 16 warps = (half h, col-group cg of 16).
    {
        int h = w >> 3;
        int cg = w & 7;
        int cg2 = lane >> 3, dpos = lane & 7;
        int c0 = (cg << 4) + (cg2 << 2);
        int dbase = (h << 9) + (dpos << 2);

        ull acc[RPB][4];
        #pragma unroll
        for (int r = 0; r < RPB; ++r)
            #pragma unroll
            for (int q = 0; q < 4; ++q) acc[r][q] = 0ull;

        const float* A0 = g_AT + c0 * Dm + dbase;
        #pragma unroll 2
        for (int it = 0; it < 16; ++it) {
            int d = it << 5;
            ulonglong2 a0 = *(const ulonglong2*)(A0 + d);
            ulonglong2 a1 = *(const ulonglong2*)(A0 + Dm + d);
            ulonglong2 a2 = *(const ulonglong2*)(A0 + 2 * Dm + d);
            ulonglong2 a3 = *(const ulonglong2*)(A0 + 3 * Dm + d);
            #pragma unroll
            for (int r = 0; r < RPB; ++r) {
                ulonglong2 xp = *(const ulonglong2*)&xs[r * Dm + dbase + d];
                fma2(acc[r][0], xp.x, a0.x); fma2(acc[r][0], xp.y, a0.y);
                fma2(acc[r][1], xp.x, a1.x); fma2(acc[r][1], xp.y, a1.y);
                fma2(acc[r][2], xp.x, a2.x); fma2(acc[r][2], xp.y, a2.y);
                fma2(acc[r][3], xp.x, a3.x); fma2(acc[r][3], xp.y, a3.y);
            }
        }
        #pragma unroll
        for (int r = 0; r < RPB; ++r) {
            #pragma unroll
            for (int q = 0; q < 4; ++q) {
                float2 p = unpack2(acc[r][q]);
                float s = p.x + p.y;
                s += __shfl_xor_sync(0xffffffffu, s, 1);
                s += __shfl_xor_sync(0xffffffffu, s, 2);
                s += __shfl_xor_sync(0xffffffffu, s, 4);
                if (dpos == 0) sp2[h][r * 128 + c0 + q] = s;
            }
        }
    }
    __syncthreads();

    float thr = thr_p[0];
    float b2v = b2p[0];

    // ---- filter + polynomial score: threads 0..255 own (r,k) pairs
    if (t < RPB * 64) {
        int r = t >> 6, k = t & 63;
        int c = (row0 + r) & 511;
        float re = sp2[0][r * 128 + k]      + sp2[1][r * 128 + k];
        float im = sp2[0][r * 128 + 64 + k] + sp2[1][r * 128 + 64 + k];
        float gr = Gr[c * Kk + k], gi = Gi[c * Kk + k];
        float lr = Lr[c * Kk + k], li = Li[c * Kk + k];
        float pw = fmaf(re, re, im * im);
        float fg = fmaf(re, gr, -im * gi);
        float fl = fmaf(re, lr, -im * li);
        float fr = (pw > thr) ? (fg + fl) : fg;
        float s = ac[10 * Kk + k];
        #pragma unroll
        for (int j = 9; j >= 0; --j) s = fmaf(s, fr, ac[j * Kk + k]);
        s += b2v;
        sp2[0][r * 128 + k]      = s;    // score
        sp2[0][r * 128 + 64 + k] = fr;   // fr
    }
    __syncthreads();

    // ---- softmax per row (warps 0..3), write duplicated (a,a) pairs
    if (w < RPB) {
        float s0 = sp2[0][w * 128 + lane],      s1 = sp2[0][w * 128 + 32 + lane];
        float f0 = sp2[0][w * 128 + 64 + lane], f1 = sp2[0][w * 128 + 96 + lane];
        float mx = fmaxf(s0, s1);
        #pragma unroll
        for (int off = 16; off; off >>= 1)
            mx = fmaxf(mx, __shfl_xor_sync(0xffffffffu, mx, off));
        float e0 = __expf(s0 - mx), e1 = __expf(s1 - mx);
        float sm = e0 + e1;
        #pragma unroll
        for (int off = 16; off; off >>= 1)
            sm += __shfl_xor_sync(0xffffffffu, sm, off);
        float inv = 1.0f / sm;
        float a0 = e0 * inv * f0;
        float a1 = e1 * inv * f1;
        int i0 = lane * (RPB * 2) + w * 2;
        int i1 = (32 + lane) * (RPB * 2) + w * 2;
        as2[i0] = a0; as2[i0 + 1] = a0;
        as2[i1] = a1; as2[i1 + 1] = a1;
    }
    __syncthreads();

    // ---- pooled (f32x2 packed FMA) + LN in registers
    {
        int d0 = t * 2;
        ull acc[RPB];
        #pragma unroll
        for (int r = 0; r < RPB; ++r)
            acc[r] = *(const ull*)&xs[r * Dm + d0];
        #pragma unroll 4
        for (int k = 0; k < 64; ++k) {
            ull ev = *(const ull*)&E[k * Dm + d0];
            const ulonglong2* aw = (const ulonglong2*)&as2[k * (RPB * 2)];
            ulonglong2 aw01 = aw[0];
            ulonglong2 aw23 = aw[1];
            fma2(acc[0], ev, aw01.x);
            fma2(acc[1], ev, aw01.y);
            fma2(acc[2], ev, aw23.x);
            fma2(acc[3], ev, aw23.y);
        }
        float2 v[RPB];
        #pragma unroll
        for (int r = 0; r < RPB; ++r) {
            v[r] = unpack2(acc[r]);
            float a = v[r].x + v[r].y;
            float b = fmaf(v[r].x, v[r].x, v[r].y * v[r].y);
            #pragma unroll
            for (int off = 16; off; off >>= 1) {
                a += __shfl_xor_sync(0xffffffffu, a, off);
                b += __shfl_xor_sync(0xffffffffu, b, off);
            }
            if (lane == 0) { red1[r][w] = a; red2[r][w] = b; }
        }
        __syncthreads();
        if (t < RPB) {
            float s1 = 0.f, s2 = 0.f;
            #pragma unroll
            for (int i = 0; i < 16; ++i) { s1 += red1[t][i]; s2 += red2[t][i]; }
            float mean = s1 * (1.0f / 1024.0f);
            float var = fmaf(-mean, mean, s2 * (1.0f / 1024.0f));
            rmean[t] = mean;
            rrstd[t] = rsqrtf(var + 1e-5f);
        }
        __syncthreads();

        float2 g2 = *(const float2*)&gamma[d0];
        float2 b2g = *(const float2*)&beta[d0];
        #pragma unroll
        for (int r = 0; r < RPB; ++r) {
            float mu = rmean[r], rs = rrstd[r];
            float2 o;
            o.x = fmaf((v[r].x - mu) * rs, g2.x, b2g.x);
            o.y = fmaf((v[r].y - mu) * rs, g2.y, b2g.y);
            *(float2*)&out[(row0 + r) * Dm + d0] = o;
        }
    }
}

// ---------------------------------------------------------------------------
extern "C" void kernel_launch(void* const* d_in, const int* in_sizes, int n_in,
                              void* d_out, int out_size) {
    const float* tokens = (const float*)d_in[0];
    const float* thresh = (const float*)d_in[1];
    const float* P      = (const float*)d_in[2];
    const float* Gr     = (const float*)d_in[3];
    const float* Gi     = (const float*)d_in[4];
    const float* Lr     = (const float*)d_in[5];
    const float* Li     = (const float*)d_in[6];
    const float* E      = (const float*)d_in[7];
    const float* W1     = (const float*)d_in[8];
    const float* b1     = (const float*)d_in[9];
    const float* w2     = (const float*)d_in[10];
    const float* b2     = (const float*)d_in[11];
    const float* gamma  = (const float*)d_in[12];
    const float* beta   = (const float*)d_in[13];
    float* out = (float*)d_out;

    k_pre<<<640, 256>>>(P, E, W1);
    k_powred<<<192, 256>>>(b1, w2);
    k_main<<<NROWS / RPB, 512>>>(tokens, thresh, Gr, Gi, Lr, Li, E,
                                 b2, gamma, beta, out);
}

// round 12
// speedup vs baseline: 1.0959x; 1.0959x over previous
#include <cuda_runtime.h>
#include <cuda_bf16.h>

// ---------------------------------------------------------------------------
// AdaptiveSpectralBlock: B=2, C=512, D=1024, K=64, FB=513
//   spectrum = tokens @ A   (A precomputed from DFT x P, stored transposed)
//   fr = Re(spectrum*gw + spectrum*mask*lw)
//   score[k](t=fr) = b2 + sum_j t^j * Acoef[j][k]   (exact-GELU Taylor moments)
//   weights = softmax_k(score); pooled = (weights*fr) @ E; out = LN(tokens+pooled)
// ---------------------------------------------------------------------------

#define Dm 1024
#define Kk 64
#define FB 513
#define NROWS 1024            // B*C
#define RPB 4                 // rows per k_main block
#define NJ 11                 // poly degree 0..10
#define NSPLIT 8              // j-splits in E@W1 GEMM

typedef unsigned long long ull;

// scratch (allocation-free rule: __device__ globals)
__device__ float g_AT[128 * Dm];                // [col][d]; col 0..63 re, 64..127 im
__device__ float g_Mpart2[NSPLIT * Kk * Dm];    // partial m[k][d] per j-split
__device__ float g_Acoef[NJ * Kk];              // [j][k]

// gelu(y) = 0.5y + (1/sqrt(2pi)) (y^2 - y^4/6 + y^6/40 - y^8/336 + y^10/3456)
__constant__ float c_cp[NJ] = {
    0.0f, 0.5f,
    0.39894228040143270f, 0.0f,
   -0.06649038006690545f, 0.0f,
    0.00997355701003582f, 0.0f,
   -0.00118732821548045f, 0.0f,
    1.1543006956058354e-4f
};
__constant__ float c_binom[NJ][NJ] = {
    {1,0,0,0,0,0,0,0,0,0,0},
    {1,1,0,0,0,0,0,0,0,0,0},
    {1,2,1,0,0,0,0,0,0,0,0},
    {1,3,3,1,0,0,0,0,0,0,0},
    {1,4,6,4,1,0,0,0,0,0,0},
    {1,5,10,10,5,1,0,0,0,0,0},
    {1,6,15,20,15,6,1,0,0,0,0},
    {1,7,21,35,35,21,7,1,0,0,0},
    {1,8,28,56,70,56,28,8,1,0,0},
    {1,9,36,84,126,126,84,36,9,1,0},
    {1,10,45,120,210,252,210,120,45,10,1}
};

__device__ __forceinline__ void fma2(ull& acc, ull a, ull b) {
    asm("fma.rn.f32x2 %0, %1, %2, %0;" : "+l"(acc) : "l"(a), "l"(b));
}
__device__ __forceinline__ ull dup2(float v) {
    ull r;
    asm("mov.b64 %0, {%1, %1};" : "=l"(r) : "f"(v));
    return r;
}
__device__ __forceinline__ float2 unpack2(ull v) {
    float2 r;
    asm("mov.b64 {%0, %1}, %2;" : "=f"(r.x), "=f"(r.y) : "l"(v));
    return r;
}

// ---------------------------------------------------------------------------
// K_pre: fused precompute.
//   blocks [0,128):   buildA: A^T[col][d] for d-group of 8 (trig tile in smem,
//                     no index recurrence, no per-iter ALU)
//   blocks [128,256): m = E @ W1 split-K GEMM partials
// ---------------------------------------------------------------------------
__global__ void __launch_bounds__(256) k_pre(const float* __restrict__ P,
                                             const float* __restrict__ E,
                                             const float* __restrict__ W1) {
    __shared__ __align__(16) char sm[40960];
    int t = threadIdx.x;

    if (blockIdx.x < 128) {
        // ---------------- buildA role ----------------
        float2* tw = (float2*)sm;                  // 8KB trig tile [ff][dd] (cos,-sin)
        float*  sP = (float*)(sm + 8192);          // 32KB P f-tile (128 f x 64 k)

        int k = t & 63, dq = t >> 6;
        int d0 = blockIdx.x * 8;
        int da = d0 + dq, db = da + 4;
        ull accA = 0ull, accB = 0ull;              // (re, im) pairs

        const float4* P4 = (const float4*)P;
        for (int f0 = 0; f0 < 512; f0 += 128) {
            __syncthreads();                       // protect smem reuse
            #pragma unroll
            for (int i = 0; i < 8; ++i) {
                int lin4 = t + i * 256;            // 2048 float4 = 128 f x 16
                ((float4*)sP)[lin4] = P4[f0 * 16 + lin4];
            }
            // trig tile: 1024 entries (128 ff x 8 dd), 4 per thread.
            // arg = (f*d)/512; f*d < 2^23 so float product and *2^-9 are exact.
            #pragma unroll
            for (int i = 0; i < 4; ++i) {
                int lin = t + i * 256;
                int ff = lin >> 3, dd = lin & 7;
                float arg = (float)((f0 + ff) * (d0 + dd)) * (1.0f / 512.0f);
                float s, c;
                sincospif(arg, &s, &c);
                tw[lin] = make_float2(c, -s);
            }
            __syncthreads();
            #pragma unroll 8
            for (int ff = 0; ff < 128; ++ff) {
                ull pvd = dup2(sP[ff * 64 + k]);
                ull wa = *(const ull*)&tw[ff * 8 + dq];
                ull wb = *(const ull*)&tw[ff * 8 + dq + 4];
                fma2(accA, wa, pvd);
                fma2(accB, wb, pvd);
            }
        }
        float2 ab = unpack2(accA);
        float2 bb = unpack2(accB);
        float ara = ab.x, aia = ab.y, arb = bb.x, aib = bb.y;

        // Nyquist bin f=512: angle = pi*d -> cos = (-1)^d, sin = 0
        float pn = P[512 * 64 + k];
        float sgn = (da & 1) ? -1.f : 1.f;
        ara = fmaf(sgn, pn, ara);
        arb = fmaf(sgn, pn, arb);

        g_AT[k * Dm + da]        = ara;
        g_AT[(64 + k) * Dm + da] = aia;
        g_AT[k * Dm + db]        = arb;
        g_AT[(64 + k) * Dm + db] = aib;
    } else {
        // ---------------- gemm role ----------------
        float* sE = (float*)sm;                    // 64x36 (9216B)
        float* sW = (float*)(sm + 9216);           // 32x64 (8192B)
        int bid = blockIdx.x - 128;
        int bd = bid & 15, bj = bid >> 4;
        int d0 = bd * 64, j0 = bj * 128;
        int tk = (t >> 4) * 4;
        int tc = t & 15;
        int td = tc * 4;

        ull acc[4][2];
        #pragma unroll
        for (int r = 0; r < 4; ++r) { acc[r][0] = 0ull; acc[r][1] = 0ull; }

        const float4* E4 = (const float4*)E;
        const float4* W14 = (const float4*)W1;

        for (int js = 0; js < 128; js += 32) {
            __syncthreads();
            #pragma unroll
            for (int i = 0; i < 2; ++i) {
                int lin4 = t + i * 256;
                int kr = lin4 >> 3, jc = lin4 & 7;
                float4 v = E4[kr * 256 + ((j0 + js) >> 2) + jc];
                *(float4*)&sE[kr * 36 + jc * 4] = v;
            }
            #pragma unroll
            for (int i = 0; i < 2; ++i) {
                int lin4 = t + i * 256;
                int jr = lin4 >> 4, dc = lin4 & 15;
                float4 v = W14[(j0 + js + jr) * 256 + (d0 >> 2) + dc];
                ((float4*)sW)[jr * 16 + dc] = v;
            }
            __syncthreads();
            #pragma unroll
            for (int jj = 0; jj < 32; ++jj) {
                ulonglong2 wp = ((const ulonglong2*)sW)[jj * 8 + tc];
                ull e0 = dup2(sE[(tk + 0) * 36 + jj]);
                ull e1 = dup2(sE[(tk + 1) * 36 + jj]);
                ull e2 = dup2(sE[(tk + 2) * 36 + jj]);
                ull e3 = dup2(sE[(tk + 3) * 36 + jj]);
                fma2(acc[0][0], e0, wp.x); fma2(acc[0][1], e0, wp.y);
                fma2(acc[1][0], e1, wp.x); fma2(acc[1][1], e1, wp.y);
                fma2(acc[2][0], e2, wp.x); fma2(acc[2][1], e2, wp.y);
                fma2(acc[3][0], e3, wp.x); fma2(acc[3][1], e3, wp.y);
            }
        }
        #pragma unroll
        for (int r = 0; r < 4; ++r) {
            ulonglong2 o; o.x = acc[r][0]; o.y = acc[r][1];
            *(ulonglong2*)&g_Mpart2[((bj << 6) + tk + r) * Dm + d0 + td] = o;
        }
    }
}

// ----------- K2: reduce partials -> m; moments Acoef[j][k] (WG inline)
__global__ void __launch_bounds__(256) k_powred(const float* __restrict__ b1,
                                                const float* __restrict__ w2) {
    __shared__ float red[8][NJ];
    int k = blockIdx.x, t = threadIdx.x;
    int d = t * 4;
    int w = t >> 5, lane = t & 31;

    float4 m4 = make_float4(0.f, 0.f, 0.f, 0.f);
    #pragma unroll
    for (int p = 0; p < NSPLIT; ++p) {
        float4 v = *(const float4*)&g_Mpart2[((p << 6) + k) * Dm + d];
        m4.x += v.x; m4.y += v.y; m4.z += v.z; m4.w += v.w;
    }
    float4 b4 = *(const float4*)&b1[d];
    float4 w4 = *(const float4*)&w2[d];

    float accj[NJ];
    #pragma unroll
    for (int j = 0; j < NJ; ++j) accj[j] = 0.f;

    float mlane[4] = {m4.x, m4.y, m4.z, m4.w};
    float blane[4] = {b4.x, b4.y, b4.z, b4.w};
    float wlane[4] = {w4.x, w4.y, w4.z, w4.w};
    #pragma unroll
    for (int q = 0; q < 4; ++q) {
        float bb = blane[q], ww = wlane[q], mm = mlane[q];
        float bp[NJ];
        bp[0] = 1.f;
        #pragma unroll
        for (int i = 1; i < NJ; ++i) bp[i] = bp[i - 1] * bb;
        float mp = 1.f;
        #pragma unroll
        for (int j = 0; j < NJ; ++j) {
            float gj = 0.f;
            #pragma unroll
            for (int p = 0; p < NJ; ++p) {
                if (p >= j) gj = fmaf(c_cp[p] * c_binom[p][j], bp[p - j], gj);
            }
            accj[j] = fmaf(ww * gj, mp, accj[j]);
            mp *= mm;
        }
    }
    #pragma unroll
    for (int j = 0; j < NJ; ++j) {
        float a = accj[j];
        #pragma unroll
        for (int off = 16; off; off >>= 1)
            a += __shfl_xor_sync(0xffffffffu, a, off);
        if (lane == 0) red[w][j] = a;
    }
    __syncthreads();
    if (t < NJ) {
        float s = 0.f;
        #pragma unroll
        for (int i = 0; i < 8; ++i) s += red[i][t];
        g_Acoef[t * Kk + k] = s;
    }
}

// ------------------------------------------------------- K3: fused main
// grid 256 blocks x 512 threads, 4 rows per block, 2 CTAs/SM.
__global__ void __launch_bounds__(512, 2) k_main(
    const float* __restrict__ tokens, const float* __restrict__ thr_p,
    const float* __restrict__ Gr, const float* __restrict__ Gi,
    const float* __restrict__ Lr, const float* __restrict__ Li,
    const float* __restrict__ E, const float* __restrict__ b2p,
    const float* __restrict__ gamma, const float* __restrict__ beta,
    float* __restrict__ out)
{
    __shared__ float xs[RPB * Dm];              // 16KB tokens
    __shared__ float sp2[2][RPB * 128];         // depth-half spectrum partials
    __shared__ float as2[Kk * RPB * 2];         // weight*fr dup pairs [k][r][2]
    __shared__ float ac[NJ * Kk];
    __shared__ float red1[RPB][16], red2[RPB][16];
    __shared__ float rmean[RPB], rrstd[RPB];

    int t = threadIdx.x;
    int row0 = blockIdx.x * RPB;
    int w = t >> 5, lane = t & 31;

    // ---- stage tokens + coefficients
    {
        const float4* tok4 = (const float4*)(tokens + row0 * Dm);
        float4* xs4 = (float4*)xs;
        #pragma unroll
        for (int i = 0; i < 2; ++i) xs4[t + i * 512] = tok4[t + i * 512];
        for (int i = t; i < NJ * Kk; i += 512) ac[i] = g_Acoef[i];
    }
    __syncthreads();

    // ---- spectrum (tokens @ A): 16 warps = (half h, col-group cg of 16).
    {
        int h = w >> 3;
        int cg = w & 7;
        int cg2 = lane >> 3, dpos = lane & 7;
        int c0 = (cg << 4) + (cg2 << 2);
        int dbase = (h << 9) + (dpos << 2);

        ull acc[RPB][4];
        #pragma unroll
        for (int r = 0; r < RPB; ++r)
            #pragma unroll
            for (int q = 0; q < 4; ++q) acc[r][q] = 0ull;

        const float* A0 = g_AT + c0 * Dm + dbase;
        #pragma unroll 2
        for (int it = 0; it < 16; ++it) {
            int d = it << 5;
            ulonglong2 a0 = *(const ulonglong2*)(A0 + d);
            ulonglong2 a1 = *(const ulonglong2*)(A0 + Dm + d);
            ulonglong2 a2 = *(const ulonglong2*)(A0 + 2 * Dm + d);
            ulonglong2 a3 = *(const ulonglong2*)(A0 + 3 * Dm + d);
            #pragma unroll
            for (int r = 0; r < RPB; ++r) {
                ulonglong2 xp = *(const ulonglong2*)&xs[r * Dm + dbase + d];
                fma2(acc[r][0], xp.x, a0.x); fma2(acc[r][0], xp.y, a0.y);
                fma2(acc[r][1], xp.x, a1.x); fma2(acc[r][1], xp.y, a1.y);
                fma2(acc[r][2], xp.x, a2.x); fma2(acc[r][2], xp.y, a2.y);
                fma2(acc[r][3], xp.x, a3.x); fma2(acc[r][3], xp.y, a3.y);
            }
        }
        #pragma unroll
        for (int r = 0; r < RPB; ++r) {
            #pragma unroll
            for (int q = 0; q < 4; ++q) {
                float2 p = unpack2(acc[r][q]);
                float s = p.x + p.y;
                s += __shfl_xor_sync(0xffffffffu, s, 1);
                s += __shfl_xor_sync(0xffffffffu, s, 2);
                s += __shfl_xor_sync(0xffffffffu, s, 4);
                if (dpos == 0) sp2[h][r * 128 + c0 + q] = s;
            }
        }
    }
    __syncthreads();

    float thr = thr_p[0];
    float b2v = b2p[0];

    // ---- filter + polynomial score: threads 0..255 own (r,k) pairs
    if (t < RPB * 64) {
        int r = t >> 6, k = t & 63;
        int c = (row0 + r) & 511;
        float re = sp2[0][r * 128 + k]      + sp2[1][r * 128 + k];
        float im = sp2[0][r * 128 + 64 + k] + sp2[1][r * 128 + 64 + k];
        float gr = Gr[c * Kk + k], gi = Gi[c * Kk + k];
        float lr = Lr[c * Kk + k], li = Li[c * Kk + k];
        float pw = fmaf(re, re, im * im);
        float fg = fmaf(re, gr, -im * gi);
        float fl = fmaf(re, lr, -im * li);
        float fr = (pw > thr) ? (fg + fl) : fg;
        float s = ac[10 * Kk + k];
        #pragma unroll
        for (int j = 9; j >= 0; --j) s = fmaf(s, fr, ac[j * Kk + k]);
        s += b2v;
        sp2[0][r * 128 + k]      = s;    // score
        sp2[0][r * 128 + 64 + k] = fr;   // fr
    }
    __syncthreads();

    // ---- softmax per row (warps 0..3), write duplicated (a,a) pairs
    if (w < RPB) {
        float s0 = sp2[0][w * 128 + lane],      s1 = sp2[0][w * 128 + 32 + lane];
        float f0 = sp2[0][w * 128 + 64 + lane], f1 = sp2[0][w * 128 + 96 + lane];
        float mx = fmaxf(s0, s1);
        #pragma unroll
        for (int off = 16; off; off >>= 1)
            mx = fmaxf(mx, __shfl_xor_sync(0xffffffffu, mx, off));
        float e0 = __expf(s0 - mx), e1 = __expf(s1 - mx);
        float sm = e0 + e1;
        #pragma unroll
        for (int off = 16; off; off >>= 1)
            sm += __shfl_xor_sync(0xffffffffu, sm, off);
        float inv = 1.0f / sm;
        float a0 = e0 * inv * f0;
        float a1 = e1 * inv * f1;
        int i0 = lane * (RPB * 2) + w * 2;
        int i1 = (32 + lane) * (RPB * 2) + w * 2;
        as2[i0] = a0; as2[i0 + 1] = a0;
        as2[i1] = a1; as2[i1 + 1] = a1;
    }
    __syncthreads();

    // ---- pooled (f32x2 packed FMA) + LN in registers
    {
        int d0 = t * 2;
        ull acc[RPB];
        #pragma unroll
        for (int r = 0; r < RPB; ++r)
            acc[r] = *(const ull*)&xs[r * Dm + d0];
        #pragma unroll 4
        for (int k = 0; k < 64; ++k) {
            ull ev = *(const ull*)&E[k * Dm + d0];
            const ulonglong2* aw = (const ulonglong2*)&as2[k * (RPB * 2)];
            ulonglong2 aw01 = aw[0];
            ulonglong2 aw23 = aw[1];
            fma2(acc[0], ev, aw01.x);
            fma2(acc[1], ev, aw01.y);
            fma2(acc[2], ev, aw23.x);
            fma2(acc[3], ev, aw23.y);
        }
        float2 v[RPB];
        #pragma unroll
        for (int r = 0; r < RPB; ++r) {
            v[r] = unpack2(acc[r]);
            float a = v[r].x + v[r].y;
            float b = fmaf(v[r].x, v[r].x, v[r].y * v[r].y);
            #pragma unroll
            for (int off = 16; off; off >>= 1) {
                a += __shfl_xor_sync(0xffffffffu, a, off);
                b += __shfl_xor_sync(0xffffffffu, b, off);
            }
            if (lane == 0) { red1[r][w] = a; red2[r][w] = b; }
        }
        __syncthreads();
        if (t < RPB) {
            float s1 = 0.f, s2 = 0.f;
            #pragma unroll
            for (int i = 0; i < 16; ++i) { s1 += red1[t][i]; s2 += red2[t][i]; }
            float mean = s1 * (1.0f / 1024.0f);
            float var = fmaf(-mean, mean, s2 * (1.0f / 1024.0f));
            rmean[t] = mean;
            rrstd[t] = rsqrtf(var + 1e-5f);
        }
        __syncthreads();

        float2 g2 = *(const float2*)&gamma[d0];
        float2 b2g = *(const float2*)&beta[d0];
        #pragma unroll
        for (int r = 0; r < RPB; ++r) {
            float mu = rmean[r], rs = rrstd[r];
            float2 o;
            o.x = fmaf((v[r].x - mu) * rs, g2.x, b2g.x);
            o.y = fmaf((v[r].y - mu) * rs, g2.y, b2g.y);
            *(float2*)&out[(row0 + r) * Dm + d0] = o;
        }
    }
}

// ---------------------------------------------------------------------------
extern "C" void kernel_launch(void* const* d_in, const int* in_sizes, int n_in,
                              void* d_out, int out_size) {
    const float* tokens = (const float*)d_in[0];
    const float* thresh = (const float*)d_in[1];
    const float* P      = (const float*)d_in[2];
    const float* Gr     = (const float*)d_in[3];
    const float* Gi     = (const float*)d_in[4];
    const float* Lr     = (const float*)d_in[5];
    const float* Li     = (const float*)d_in[6];
    const float* E      = (const float*)d_in[7];
    const float* W1     = (const float*)d_in[8];
    const float* b1     = (const float*)d_in[9];
    const float* w2     = (const float*)d_in[10];
    const float* b2     = (const float*)d_in[11];
    const float* gamma  = (const float*)d_in[12];
    const float* beta   = (const float*)d_in[13];
    float* out = (float*)d_out;

    k_pre<<<256, 256>>>(P, E, W1);
    k_powred<<<64, 256>>>(b1, w2);
    k_main<<<NROWS / RPB, 512>>>(tokens, thresh, Gr, Gi, Lr, Li, E,
                                 b2, gamma, beta, out);
}

// round 13
// speedup vs baseline: 1.1132x; 1.0158x over previous
#include <cuda_runtime.h>
#include <cuda_bf16.h>

// ---------------------------------------------------------------------------
// AdaptiveSpectralBlock: B=2, C=512, D=1024, K=64, FB=513
//   spectrum = tokens @ A   (A precomputed from DFT x P, stored transposed)
//   fr = Re(spectrum*gw + spectrum*mask*lw)
//   score[k](t=fr) = b2 + sum_j t^j * Acoef[j][k]   (exact-GELU Taylor moments)
//   weights = softmax_k(score); pooled = (weights*fr) @ E; out = LN(tokens+pooled)
// ---------------------------------------------------------------------------

#define Dm 1024
#define Kk 64
#define FB 513
#define NROWS 1024            // B*C
#define RPB 4                 // rows per k_main block
#define NJ 11                 // poly degree 0..10
#define NSPLIT 8              // j-splits in E@W1 GEMM

typedef unsigned long long ull;

// scratch (allocation-free rule: __device__ globals)
__device__ float g_AT[128 * Dm];                // [col][d]; col 0..63 re, 64..127 im
__device__ float g_Mpart2[NSPLIT * Kk * Dm];    // partial m[k][d] per j-split
__device__ float g_Acoef[NJ * Kk];              // [j][k]

// gelu(y) = 0.5y + (1/sqrt(2pi)) (y^2 - y^4/6 + y^6/40 - y^8/336 + y^10/3456)
__constant__ float c_cp[NJ] = {
    0.0f, 0.5f,
    0.39894228040143270f, 0.0f,
   -0.06649038006690545f, 0.0f,
    0.00997355701003582f, 0.0f,
   -0.00118732821548045f, 0.0f,
    1.1543006956058354e-4f
};
__constant__ float c_binom[NJ][NJ] = {
    {1,0,0,0,0,0,0,0,0,0,0},
    {1,1,0,0,0,0,0,0,0,0,0},
    {1,2,1,0,0,0,0,0,0,0,0},
    {1,3,3,1,0,0,0,0,0,0,0},
    {1,4,6,4,1,0,0,0,0,0,0},
    {1,5,10,10,5,1,0,0,0,0,0},
    {1,6,15,20,15,6,1,0,0,0,0},
    {1,7,21,35,35,21,7,1,0,0,0},
    {1,8,28,56,70,56,28,8,1,0,0},
    {1,9,36,84,126,126,84,36,9,1,0},
    {1,10,45,120,210,252,210,120,45,10,1}
};

__device__ __forceinline__ void fma2(ull& acc, ull a, ull b) {
    asm("fma.rn.f32x2 %0, %1, %2, %0;" : "+l"(acc) : "l"(a), "l"(b));
}
__device__ __forceinline__ ull dup2(float v) {
    ull r;
    asm("mov.b64 %0, {%1, %1};" : "=l"(r) : "f"(v));
    return r;
}
__device__ __forceinline__ float2 unpack2(ull v) {
    float2 r;
    asm("mov.b64 {%0, %1}, %2;" : "=f"(r.x), "=f"(r.y) : "l"(v));
    return r;
}

// ---------------------------------------------------------------------------
// K_pre: fused precompute.
//   blocks [0,128):   buildA: A^T[col][d] for d-group of 8; packed float4 trig
//                     tile -> inner loop = 1 LDS.32 + 1 broadcast LDS.128 + 2 FFMA2
//   blocks [128,256): m = E @ W1 split-K GEMM partials
// ---------------------------------------------------------------------------
__global__ void __launch_bounds__(256) k_pre(const float* __restrict__ P,
                                             const float* __restrict__ E,
                                             const float* __restrict__ W1) {
    __shared__ __align__(16) char sm[40960];
    int t = threadIdx.x;

    if (blockIdx.x < 128) {
        // ---------------- buildA role ----------------
        float4* tw4 = (float4*)sm;                 // 8KB: [ff][dq] = (ca,-sa,cb,-sb)
        float*  sP  = (float*)(sm + 8192);         // 32KB P f-tile (128 f x 64 k)

        int k = t & 63, dq = t >> 6;
        int d0 = blockIdx.x * 8;
        int da = d0 + dq, db = da + 4;
        ull accA = 0ull, accB = 0ull;              // (re, im) pairs

        const float4* P4 = (const float4*)P;
        for (int f0 = 0; f0 < 512; f0 += 128) {
            __syncthreads();                       // protect smem reuse
            #pragma unroll
            for (int i = 0; i < 8; ++i) {
                int lin4 = t + i * 256;            // 2048 float4 = 128 f x 16
                ((float4*)sP)[lin4] = P4[f0 * 16 + lin4];
            }
            // packed trig tile: 512 float4 entries (128 ff x 4 dq), 2 per thread.
            // arg = (f*d)/512 in pi-units; f*d < 2^19 so product & scaling exact.
            #pragma unroll
            for (int i = 0; i < 2; ++i) {
                int lin = t + i * 256;             // 0..511
                int ff = lin >> 2, dd = lin & 3;
                int f = f0 + ff;
                float arga = (float)(f * (d0 + dd))     * (1.0f / 512.0f);
                float argb = (float)(f * (d0 + dd + 4)) * (1.0f / 512.0f);
                float sa, ca, sb, cb;
                sincospif(arga, &sa, &ca);
                sincospif(argb, &sb, &cb);
                tw4[lin] = make_float4(ca, -sa, cb, -sb);
            }
            __syncthreads();
            #pragma unroll 8
            for (int ff = 0; ff < 128; ++ff) {
                ull pvd = dup2(sP[ff * 64 + k]);
                ulonglong2 wv = *(const ulonglong2*)&tw4[ff * 4 + dq];
                fma2(accA, wv.x, pvd);
                fma2(accB, wv.y, pvd);
            }
        }
        float2 ab = unpack2(accA);
        float2 bb = unpack2(accB);
        float ara = ab.x, aia = ab.y, arb = bb.x, aib = bb.y;

        // Nyquist bin f=512: angle = pi*d -> cos = (-1)^d, sin = 0
        float pn = P[512 * 64 + k];
        float sgn = (da & 1) ? -1.f : 1.f;
        ara = fmaf(sgn, pn, ara);
        arb = fmaf(sgn, pn, arb);

        g_AT[k * Dm + da]        = ara;
        g_AT[(64 + k) * Dm + da] = aia;
        g_AT[k * Dm + db]        = arb;
        g_AT[(64 + k) * Dm + db] = aib;
    } else {
        // ---------------- gemm role ----------------
        float* sE = (float*)sm;                    // 64x36 (9216B)
        float* sW = (float*)(sm + 9216);           // 32x64 (8192B)
        int bid = blockIdx.x - 128;
        int bd = bid & 15, bj = bid >> 4;
        int d0 = bd * 64, j0 = bj * 128;
        int tk = (t >> 4) * 4;
        int tc = t & 15;
        int td = tc * 4;

        ull acc[4][2];
        #pragma unroll
        for (int r = 0; r < 4; ++r) { acc[r][0] = 0ull; acc[r][1] = 0ull; }

        const float4* E4 = (const float4*)E;
        const float4* W14 = (const float4*)W1;

        for (int js = 0; js < 128; js += 32) {
            __syncthreads();
            #pragma unroll
            for (int i = 0; i < 2; ++i) {
                int lin4 = t + i * 256;
                int kr = lin4 >> 3, jc = lin4 & 7;
                float4 v = E4[kr * 256 + ((j0 + js) >> 2) + jc];
                *(float4*)&sE[kr * 36 + jc * 4] = v;
            }
            #pragma unroll
            for (int i = 0; i < 2; ++i) {
                int lin4 = t + i * 256;
                int jr = lin4 >> 4, dc = lin4 & 15;
                float4 v = W14[(j0 + js + jr) * 256 + (d0 >> 2) + dc];
                ((float4*)sW)[jr * 16 + dc] = v;
            }
            __syncthreads();
            #pragma unroll
            for (int jj = 0; jj < 32; ++jj) {
                ulonglong2 wp = ((const ulonglong2*)sW)[jj * 8 + tc];
                ull e0 = dup2(sE[(tk + 0) * 36 + jj]);
                ull e1 = dup2(sE[(tk + 1) * 36 + jj]);
                ull e2 = dup2(sE[(tk + 2) * 36 + jj]);
                ull e3 = dup2(sE[(tk + 3) * 36 + jj]);
                fma2(acc[0][0], e0, wp.x); fma2(acc[0][1], e0, wp.y);
                fma2(acc[1][0], e1, wp.x); fma2(acc[1][1], e1, wp.y);
                fma2(acc[2][0], e2, wp.x); fma2(acc[2][1], e2, wp.y);
                fma2(acc[3][0], e3, wp.x); fma2(acc[3][1], e3, wp.y);
            }
        }
        #pragma unroll
        for (int r = 0; r < 4; ++r) {
            ulonglong2 o; o.x = acc[r][0]; o.y = acc[r][1];
            *(ulonglong2*)&g_Mpart2[((bj << 6) + tk + r) * Dm + d0 + td] = o;
        }
    }
}

// ----------- K2: reduce partials -> m; moments Acoef[j][k] (WG inline)
__global__ void __launch_bounds__(256) k_powred(const float* __restrict__ b1,
                                                const float* __restrict__ w2) {
    __shared__ float red[8][NJ];
    int k = blockIdx.x, t = threadIdx.x;
    int d = t * 4;
    int w = t >> 5, lane = t & 31;

    float4 m4 = make_float4(0.f, 0.f, 0.f, 0.f);
    #pragma unroll
    for (int p = 0; p < NSPLIT; ++p) {
        float4 v = *(const float4*)&g_Mpart2[((p << 6) + k) * Dm + d];
        m4.x += v.x; m4.y += v.y; m4.z += v.z; m4.w += v.w;
    }
    float4 b4 = *(const float4*)&b1[d];
    float4 w4 = *(const float4*)&w2[d];

    float accj[NJ];
    #pragma unroll
    for (int j = 0; j < NJ; ++j) accj[j] = 0.f;

    float mlane[4] = {m4.x, m4.y, m4.z, m4.w};
    float blane[4] = {b4.x, b4.y, b4.z, b4.w};
    float wlane[4] = {w4.x, w4.y, w4.z, w4.w};
    #pragma unroll
    for (int q = 0; q < 4; ++q) {
        float bb = blane[q], ww = wlane[q], mm = mlane[q];
        float bp[NJ];
        bp[0] = 1.f;
        #pragma unroll
        for (int i = 1; i < NJ; ++i) bp[i] = bp[i - 1] * bb;
        float mp = 1.f;
        #pragma unroll
        for (int j = 0; j < NJ; ++j) {
            float gj = 0.f;
            #pragma unroll
            for (int p = 0; p < NJ; ++p) {
                if (p >= j) gj = fmaf(c_cp[p] * c_binom[p][j], bp[p - j], gj);
            }
            accj[j] = fmaf(ww * gj, mp, accj[j]);
            mp *= mm;
        }
    }
    #pragma unroll
    for (int j = 0; j < NJ; ++j) {
        float a = accj[j];
        #pragma unroll
        for (int off = 16; off; off >>= 1)
            a += __shfl_xor_sync(0xffffffffu, a, off);
        if (lane == 0) red[w][j] = a;
    }
    __syncthreads();
    if (t < NJ) {
        float s = 0.f;
        #pragma unroll
        for (int i = 0; i < 8; ++i) s += red[i][t];
        g_Acoef[t * Kk + k] = s;
    }
}

// ------------------------------------------------------- K3: fused main
// grid 256 blocks x 512 threads, 4 rows per block, 2 CTAs/SM.
__global__ void __launch_bounds__(512, 2) k_main(
    const float* __restrict__ tokens, const float* __restrict__ thr_p,
    const float* __restrict__ Gr, const float* __restrict__ Gi,
    const float* __restrict__ Lr, const float* __restrict__ Li,
    const float* __restrict__ E, const float* __restrict__ b2p,
    const float* __restrict__ gamma, const float* __restrict__ beta,
    float* __restrict__ out)
{
    __shared__ float xs[RPB * Dm];              // 16KB tokens
    __shared__ float sp2[2][RPB * 128];         // depth-half spectrum partials
    __shared__ float as2[Kk * RPB * 2];         // weight*fr dup pairs [k][r][2]
    __shared__ float ac[NJ * Kk];
    __shared__ float red1[RPB][16], red2[RPB][16];
    __shared__ float rmean[RPB], rrstd[RPB];

    int t = threadIdx.x;
    int row0 = blockIdx.x * RPB;
    int w = t >> 5, lane = t & 31;

    // ---- stage tokens + coefficients
    {
        const float4* tok4 = (const float4*)(tokens + row0 * Dm);
        float4* xs4 = (float4*)xs;
        #pragma unroll
        for (int i = 0; i < 2; ++i) xs4[t + i * 512] = tok4[t + i * 512];
        for (int i = t; i < NJ * Kk; i += 512) ac[i] = g_Acoef[i];
    }
    __syncthreads();

    // ---- spectrum (tokens @ A): 16 warps = (half h, col-group cg of 16).
    {
        int h = w >> 3;
        int cg = w & 7;
        int cg2 = lane >> 3, dpos = lane & 7;
        int c0 = (cg << 4) + (cg2 << 2);
        int dbase = (h << 9) + (dpos << 2);

        ull acc[RPB][4];
        #pragma unroll
        for (int r = 0; r < RPB; ++r)
            #pragma unroll
            for (int q = 0; q < 4; ++q) acc[r][q] = 0ull;

        const float* A0 = g_AT + c0 * Dm + dbase;
        #pragma unroll 2
        for (int it = 0; it < 16; ++it) {
            int d = it << 5;
            ulonglong2 a0 = *(const ulonglong2*)(A0 + d);
            ulonglong2 a1 = *(const ulonglong2*)(A0 + Dm + d);
            ulonglong2 a2 = *(const ulonglong2*)(A0 + 2 * Dm + d);
            ulonglong2 a3 = *(const ulonglong2*)(A0 + 3 * Dm + d);
            #pragma unroll
            for (int r = 0; r < RPB; ++r) {
                ulonglong2 xp = *(const ulonglong2*)&xs[r * Dm + dbase + d];
                fma2(acc[r][0], xp.x, a0.x); fma2(acc[r][0], xp.y, a0.y);
                fma2(acc[r][1], xp.x, a1.x); fma2(acc[r][1], xp.y, a1.y);
                fma2(acc[r][2], xp.x, a2.x); fma2(acc[r][2], xp.y, a2.y);
                fma2(acc[r][3], xp.x, a3.x); fma2(acc[r][3], xp.y, a3.y);
            }
        }
        #pragma unroll
        for (int r = 0; r < RPB; ++r) {
            #pragma unroll
            for (int q = 0; q < 4; ++q) {
                float2 p = unpack2(acc[r][q]);
                float s = p.x + p.y;
                s += __shfl_xor_sync(0xffffffffu, s, 1);
                s += __shfl_xor_sync(0xffffffffu, s, 2);
                s += __shfl_xor_sync(0xffffffffu, s, 4);
                if (dpos == 0) sp2[h][r * 128 + c0 + q] = s;
            }
        }
    }
    __syncthreads();

    float thr = thr_p[0];
    float b2v = b2p[0];

    // ---- filter + polynomial score: threads 0..255 own (r,k) pairs
    if (t < RPB * 64) {
        int r = t >> 6, k = t & 63;
        int c = (row0 + r) & 511;
        float re = sp2[0][r * 128 + k]      + sp2[1][r * 128 + k];
        float im = sp2[0][r * 128 + 64 + k] + sp2[1][r * 128 + 64 + k];
        float gr = Gr[c * Kk + k], gi = Gi[c * Kk + k];
        float lr = Lr[c * Kk + k], li = Li[c * Kk + k];
        float pw = fmaf(re, re, im * im);
        float fg = fmaf(re, gr, -im * gi);
        float fl = fmaf(re, lr, -im * li);
        float fr = (pw > thr) ? (fg + fl) : fg;
        float s = ac[10 * Kk + k];
        #pragma unroll
        for (int j = 9; j >= 0; --j) s = fmaf(s, fr, ac[j * Kk + k]);
        s += b2v;
        sp2[0][r * 128 + k]      = s;    // score
        sp2[0][r * 128 + 64 + k] = fr;   // fr
    }
    __syncthreads();

    // ---- softmax per row (warps 0..3), write duplicated (a,a) pairs
    if (w < RPB) {
        float s0 = sp2[0][w * 128 + lane],      s1 = sp2[0][w * 128 + 32 + lane];
        float f0 = sp2[0][w * 128 + 64 + lane], f1 = sp2[0][w * 128 + 96 + lane];
        float mx = fmaxf(s0, s1);
        #pragma unroll
        for (int off = 16; off; off >>= 1)
            mx = fmaxf(mx, __shfl_xor_sync(0xffffffffu, mx, off));
        float e0 = __expf(s0 - mx), e1 = __expf(s1 - mx);
        float sm = e0 + e1;
        #pragma unroll
        for (int off = 16; off; off >>= 1)
            sm += __shfl_xor_sync(0xffffffffu, sm, off);
        float inv = 1.0f / sm;
        float a0 = e0 * inv * f0;
        float a1 = e1 * inv * f1;
        int i0 = lane * (RPB * 2) + w * 2;
        int i1 = (32 + lane) * (RPB * 2) + w * 2;
        as2[i0] = a0; as2[i0 + 1] = a0;
        as2[i1] = a1; as2[i1 + 1] = a1;
    }
    __syncthreads();

    // ---- pooled (f32x2 packed FMA) + LN in registers
    {
        int d0 = t * 2;
        ull acc[RPB];
        #pragma unroll
        for (int r = 0; r < RPB; ++r)
            acc[r] = *(const ull*)&xs[r * Dm + d0];
        #pragma unroll 4
        for (int k = 0; k < 64; ++k) {
            ull ev = *(const ull*)&E[k * Dm + d0];
            const ulonglong2* aw = (const ulonglong2*)&as2[k * (RPB * 2)];
            ulonglong2 aw01 = aw[0];
            ulonglong2 aw23 = aw[1];
            fma2(acc[0], ev, aw01.x);
            fma2(acc[1], ev, aw01.y);
            fma2(acc[2], ev, aw23.x);
            fma2(acc[3], ev, aw23.y);
        }
        float2 v[RPB];
        #pragma unroll
        for (int r = 0; r < RPB; ++r) {
            v[r] = unpack2(acc[r]);
            float a = v[r].x + v[r].y;
            float b = fmaf(v[r].x, v[r].x, v[r].y * v[r].y);
            #pragma unroll
            for (int off = 16; off; off >>= 1) {
                a += __shfl_xor_sync(0xffffffffu, a, off);
                b += __shfl_xor_sync(0xffffffffu, b, off);
            }
            if (lane == 0) { red1[r][w] = a; red2[r][w] = b; }
        }
        __syncthreads();
        if (t < RPB) {
            float s1 = 0.f, s2 = 0.f;
            #pragma unroll
            for (int i = 0; i < 16; ++i) { s1 += red1[t][i]; s2 += red2[t][i]; }
            float mean = s1 * (1.0f / 1024.0f);
            float var = fmaf(-mean, mean, s2 * (1.0f / 1024.0f));
            rmean[t] = mean;
            rrstd[t] = rsqrtf(var + 1e-5f);
        }
        __syncthreads();

        float2 g2 = *(const float2*)&gamma[d0];
        float2 b2g = *(const float2*)&beta[d0];
        #pragma unroll
        for (int r = 0; r < RPB; ++r) {
            float mu = rmean[r], rs = rrstd[r];
            float2 o;
            o.x = fmaf((v[r].x - mu) * rs, g2.x, b2g.x);
            o.y = fmaf((v[r].y - mu) * rs, g2.y, b2g.y);
            *(float2*)&out[(row0 + r) * Dm + d0] = o;
        }
    }
}

// ---------------------------------------------------------------------------
extern "C" void kernel_launch(void* const* d_in, const int* in_sizes, int n_in,
                              void* d_out, int out_size) {
    const float* tokens = (const float*)d_in[0];
    const float* thresh = (const float*)d_in[1];
    const float* P      = (const float*)d_in[2];
    const float* Gr     = (const float*)d_in[3];
    const float* Gi     = (const float*)d_in[4];
    const float* Lr     = (const float*)d_in[5];
    const float* Li     = (const float*)d_in[6];
    const float* E      = (const float*)d_in[7];
    const float* W1     = (const float*)d_in[8];
    const float* b1     = (const float*)d_in[9];
    const float* w2     = (const float*)d_in[10];
    const float* b2     = (const float*)d_in[11];
    const float* gamma  = (const float*)d_in[12];
    const float* beta   = (const float*)d_in[13];
    float* out = (float*)d_out;

    k_pre<<<256, 256>>>(P, E, W1);
    k_powred<<<64, 256>>>(b1, w2);
    k_main<<<NROWS / RPB, 512>>>(tokens, thresh, Gr, Gi, Lr, Li, E,
                                 b2, gamma, beta, out);
}

// round 14
// speedup vs baseline: 1.1554x; 1.0379x over previous
#include <cuda_runtime.h>
#include <cuda_bf16.h>

// ---------------------------------------------------------------------------
// AdaptiveSpectralBlock: B=2, C=512, D=1024, K=64, FB=513
//   spectrum = tokens @ A   (A precomputed from DFT x P, stored transposed)
//   fr = Re(spectrum*gw + spectrum*mask*lw)
//   score[k](t=fr) = b2 + sum_j t^j * Acoef[j][k]   (exact-GELU Taylor moments)
//   weights = softmax_k(score); pooled = (weights*fr) @ E; out = LN(tokens+pooled)
// ---------------------------------------------------------------------------

#define Dm 1024
#define Kk 64
#define FB 513
#define NROWS 1024            // B*C
#define RPB 4                 // rows per k_main block
#define NJ 11                 // poly degree 0..10
#define NSPLIT 8              // j-splits in E@W1 GEMM

typedef unsigned long long ull;

// scratch (allocation-free rule: __device__ globals)
__device__ float g_AT[128 * Dm];                // [col][d]; col 0..63 re, 64..127 im
__device__ float g_Mpart2[NSPLIT * Kk * Dm];    // partial m[k][d] per j-split
__device__ float g_Acoef[NJ * Kk];              // [j][k]

// gelu(y) = 0.5y + (1/sqrt(2pi)) (y^2 - y^4/6 + y^6/40 - y^8/336 + y^10/3456)
__constant__ float c_cp[NJ] = {
    0.0f, 0.5f,
    0.39894228040143270f, 0.0f,
   -0.06649038006690545f, 0.0f,
    0.00997355701003582f, 0.0f,
   -0.00118732821548045f, 0.0f,
    1.1543006956058354e-4f
};
__constant__ float c_binom[NJ][NJ] = {
    {1,0,0,0,0,0,0,0,0,0,0},
    {1,1,0,0,0,0,0,0,0,0,0},
    {1,2,1,0,0,0,0,0,0,0,0},
    {1,3,3,1,0,0,0,0,0,0,0},
    {1,4,6,4,1,0,0,0,0,0,0},
    {1,5,10,10,5,1,0,0,0,0,0},
    {1,6,15,20,15,6,1,0,0,0,0},
    {1,7,21,35,35,21,7,1,0,0,0},
    {1,8,28,56,70,56,28,8,1,0,0},
    {1,9,36,84,126,126,84,36,9,1,0},
    {1,10,45,120,210,252,210,120,45,10,1}
};

__device__ __forceinline__ void fma2(ull& acc, ull a, ull b) {
    asm("fma.rn.f32x2 %0, %1, %2, %0;" : "+l"(acc) : "l"(a), "l"(b));
}
__device__ __forceinline__ ull dup2(float v) {
    ull r;
    asm("mov.b64 %0, {%1, %1};" : "=l"(r) : "f"(v));
    return r;
}
__device__ __forceinline__ float2 unpack2(ull v) {
    float2 r;
    asm("mov.b64 {%0, %1}, %2;" : "=f"(r.x), "=f"(r.y) : "l"(v));
    return r;
}

// ---------------------------------------------------------------------------
// K_pre: fused precompute.
//   blocks [0,128):   buildA: A^T[col][d] for d-group of 8.
//     Each thread accumulates ALL 8 d (8 f32x2 accs); the 4 k-replica groups
//     (rep = t>>6) split the f range in-block. Per iter: 1 LDS.32 + 4 broadcast
//     LDS.128 + 8 FFMA2 = 5 wf / 16 FMA. Partials combined in-block via smem.
//   blocks [128,256): m = E @ W1 split-K GEMM partials
// ---------------------------------------------------------------------------
__global__ void __launch_bounds__(256) k_pre(const float* __restrict__ P,
                                             const float* __restrict__ E,
                                             const float* __restrict__ W1) {
    __shared__ __align__(16) char sm[40960];
    int t = threadIdx.x;

    if (blockIdx.x < 128) {
        // ---------------- buildA role ----------------
        float2* tw = (float2*)sm;                  // 8KB: [ff][dd] (cos,-sin), 128x8
        float*  sP = (float*)(sm + 8192);          // 32KB P f-tile (128 f x 64 k)

        int k = t & 63, rep = t >> 6;              // rep = f-quarter within tile
        int d0 = blockIdx.x * 8;

        ull acc[8];
        #pragma unroll
        for (int q = 0; q < 8; ++q) acc[q] = 0ull;

        const float4* P4 = (const float4*)P;
        for (int f0 = 0; f0 < 512; f0 += 128) {
            __syncthreads();                       // protect smem reuse
            #pragma unroll
            for (int i = 0; i < 8; ++i) {
                int lin4 = t + i * 256;            // 2048 float4 = 128 f x 16
                ((float4*)sP)[lin4] = P4[f0 * 16 + lin4];
            }
            // trig tile: 1024 float2 (128 ff x 8 dd), 4 per thread.
            // arg = (f*d)/512 in pi-units; f*d < 2^19 so product & scaling exact.
            #pragma unroll
            for (int i = 0; i < 4; ++i) {
                int lin = t + i * 256;
                int ff = lin >> 3, dd = lin & 7;
                float arg = (float)((f0 + ff) * (d0 + dd)) * (1.0f / 512.0f);
                float s, c;
                sincospif(arg, &s, &c);
                tw[lin] = make_float2(c, -s);
            }
            __syncthreads();
            int base = rep << 5;                   // this rep's 32-ff slice
            #pragma unroll 8
            for (int f2 = 0; f2 < 32; ++f2) {
                int ff = base + f2;
                ull pvd = dup2(sP[ff * 64 + k]);
                const ulonglong2* twp = (const ulonglong2*)&tw[ff * 8];
                ulonglong2 w01 = twp[0];
                ulonglong2 w23 = twp[1];
                fma2(acc[0], w01.x, pvd); fma2(acc[1], w01.y, pvd);
                fma2(acc[2], w23.x, pvd); fma2(acc[3], w23.y, pvd);
                ulonglong2 w45 = twp[2];
                ulonglong2 w67 = twp[3];
                fma2(acc[4], w45.x, pvd); fma2(acc[5], w45.y, pvd);
                fma2(acc[6], w67.x, pvd); fma2(acc[7], w67.y, pvd);
            }
        }
        // in-block combine of the 4 rep partials (deterministic order)
        __syncthreads();
        float2* st = (float2*)(sm + 8192);         // reuse sP region (16KB)
        #pragma unroll
        for (int q = 0; q < 8; ++q)
            st[((rep << 6) + k) * 8 + q] = unpack2(acc[q]);
        __syncthreads();
        #pragma unroll
        for (int i = 0; i < 2; ++i) {
            int p = t + i * 256;                   // 0..511 = (k, dd)
            int kk = p >> 3, dd = p & 7;
            float2 s0 = st[((0 << 6) + kk) * 8 + dd];
            float2 s1 = st[((1 << 6) + kk) * 8 + dd];
            float2 s2 = st[((2 << 6) + kk) * 8 + dd];
            float2 s3 = st[((3 << 6) + kk) * 8 + dd];
            float re = (s0.x + s1.x) + (s2.x + s3.x);
            float im = (s0.y + s1.y) + (s2.y + s3.y);
            int d = d0 + dd;
            // Nyquist bin f=512: angle = pi*d -> cos = (-1)^d, sin = 0
            float pn = P[512 * 64 + kk];
            re = fmaf((d & 1) ? -1.f : 1.f, pn, re);
            g_AT[kk * Dm + d]        = re;
            g_AT[(64 + kk) * Dm + d] = im;
        }
    } else {
        // ---------------- gemm role ----------------
        float* sE = (float*)sm;                    // 64x36 (9216B)
        float* sW = (float*)(sm + 9216);           // 32x64 (8192B)
        int bid = blockIdx.x - 128;
        int bd = bid & 15, bj = bid >> 4;
        int d0 = bd * 64, j0 = bj * 128;
        int tk = (t >> 4) * 4;
        int tc = t & 15;
        int td = tc * 4;

        ull acc[4][2];
        #pragma unroll
        for (int r = 0; r < 4; ++r) { acc[r][0] = 0ull; acc[r][1] = 0ull; }

        const float4* E4 = (const float4*)E;
        const float4* W14 = (const float4*)W1;

        for (int js = 0; js < 128; js += 32) {
            __syncthreads();
            #pragma unroll
            for (int i = 0; i < 2; ++i) {
                int lin4 = t + i * 256;
                int kr = lin4 >> 3, jc = lin4 & 7;
                float4 v = E4[kr * 256 + ((j0 + js) >> 2) + jc];
                *(float4*)&sE[kr * 36 + jc * 4] = v;
            }
            #pragma unroll
            for (int i = 0; i < 2; ++i) {
                int lin4 = t + i * 256;
                int jr = lin4 >> 4, dc = lin4 & 15;
                float4 v = W14[(j0 + js + jr) * 256 + (d0 >> 2) + dc];
                ((float4*)sW)[jr * 16 + dc] = v;
            }
            __syncthreads();
            #pragma unroll
            for (int jj = 0; jj < 32; ++jj) {
                ulonglong2 wp = ((const ulonglong2*)sW)[jj * 8 + tc];
                ull e0 = dup2(sE[(tk + 0) * 36 + jj]);
                ull e1 = dup2(sE[(tk + 1) * 36 + jj]);
                ull e2 = dup2(sE[(tk + 2) * 36 + jj]);
                ull e3 = dup2(sE[(tk + 3) * 36 + jj]);
                fma2(acc[0][0], e0, wp.x); fma2(acc[0][1], e0, wp.y);
                fma2(acc[1][0], e1, wp.x); fma2(acc[1][1], e1, wp.y);
                fma2(acc[2][0], e2, wp.x); fma2(acc[2][1], e2, wp.y);
                fma2(acc[3][0], e3, wp.x); fma2(acc[3][1], e3, wp.y);
            }
        }
        #pragma unroll
        for (int r = 0; r < 4; ++r) {
            ulonglong2 o; o.x = acc[r][0]; o.y = acc[r][1];
            *(ulonglong2*)&g_Mpart2[((bj << 6) + tk + r) * Dm + d0 + td] = o;
        }
    }
}

// ----------- K2: reduce partials -> m; moments Acoef[j][k] (WG inline)
__global__ void __launch_bounds__(256) k_powred(const float* __restrict__ b1,
                                                const float* __restrict__ w2) {
    __shared__ float red[8][NJ];
    int k = blockIdx.x, t = threadIdx.x;
    int d = t * 4;
    int w = t >> 5, lane = t & 31;

    float4 m4 = make_float4(0.f, 0.f, 0.f, 0.f);
    #pragma unroll
    for (int p = 0; p < NSPLIT; ++p) {
        float4 v = *(const float4*)&g_Mpart2[((p << 6) + k) * Dm + d];
        m4.x += v.x; m4.y += v.y; m4.z += v.z; m4.w += v.w;
    }
    float4 b4 = *(const float4*)&b1[d];
    float4 w4 = *(const float4*)&w2[d];

    float accj[NJ];
    #pragma unroll
    for (int j = 0; j < NJ; ++j) accj[j] = 0.f;

    float mlane[4] = {m4.x, m4.y, m4.z, m4.w};
    float blane[4] = {b4.x, b4.y, b4.z, b4.w};
    float wlane[4] = {w4.x, w4.y, w4.z, w4.w};
    #pragma unroll
    for (int q = 0; q < 4; ++q) {
        float bb = blane[q], ww = wlane[q], mm = mlane[q];
        float bp[NJ];
        bp[0] = 1.f;
        #pragma unroll
        for (int i = 1; i < NJ; ++i) bp[i] = bp[i - 1] * bb;
        float mp = 1.f;
        #pragma unroll
        for (int j = 0; j < NJ; ++j) {
            float gj = 0.f;
            #pragma unroll
            for (int p = 0; p < NJ; ++p) {
                if (p >= j) gj = fmaf(c_cp[p] * c_binom[p][j], bp[p - j], gj);
            }
            accj[j] = fmaf(ww * gj, mp, accj[j]);
            mp *= mm;
        }
    }
    #pragma unroll
    for (int j = 0; j < NJ; ++j) {
        float a = accj[j];
        #pragma unroll
        for (int off = 16; off; off >>= 1)
            a += __shfl_xor_sync(0xffffffffu, a, off);
        if (lane == 0) red[w][j] = a;
    }
    __syncthreads();
    if (t < NJ) {
        float s = 0.f;
        #pragma unroll
        for (int i = 0; i < 8; ++i) s += red[i][t];
        g_Acoef[t * Kk + k] = s;
    }
}

// ------------------------------------------------------- K3: fused main
// grid 256 blocks x 512 threads, 4 rows per block, 2 CTAs/SM.
__global__ void __launch_bounds__(512, 2) k_main(
    const float* __restrict__ tokens, const float* __restrict__ thr_p,
    const float* __restrict__ Gr, const float* __restrict__ Gi,
    const float* __restrict__ Lr, const float* __restrict__ Li,
    const float* __restrict__ E, const float* __restrict__ b2p,
    const float* __restrict__ gamma, const float* __restrict__ beta,
    float* __restrict__ out)
{
    __shared__ float xs[RPB * Dm];              // 16KB tokens
    __shared__ float sp2[2][RPB * 128];         // depth-half spectrum partials
    __shared__ float as2[Kk * RPB * 2];         // weight*fr dup pairs [k][r][2]
    __shared__ float ac[NJ * Kk];
    __shared__ float red1[RPB][16], red2[RPB][16];
    __shared__ float rmean[RPB], rrstd[RPB];

    int t = threadIdx.x;
    int row0 = blockIdx.x * RPB;
    int w = t >> 5, lane = t & 31;

    // ---- stage tokens + coefficients
    {
        const float4* tok4 = (const float4*)(tokens + row0 * Dm);
        float4* xs4 = (float4*)xs;
        #pragma unroll
        for (int i = 0; i < 2; ++i) xs4[t + i * 512] = tok4[t + i * 512];
        for (int i = t; i < NJ * Kk; i += 512) ac[i] = g_Acoef[i];
    }
    __syncthreads();

    // ---- spectrum (tokens @ A): 16 warps = (half h, col-group cg of 16).
    {
        int h = w >> 3;
        int cg = w & 7;
        int cg2 = lane >> 3, dpos = lane & 7;
        int c0 = (cg << 4) + (cg2 << 2);
        int dbase = (h << 9) + (dpos << 2);

        ull acc[RPB][4];
        #pragma unroll
        for (int r = 0; r < RPB; ++r)
            #pragma unroll
            for (int q = 0; q < 4; ++q) acc[r][q] = 0ull;

        const float* A0 = g_AT + c0 * Dm + dbase;
        #pragma unroll 2
        for (int it = 0; it < 16; ++it) {
            int d = it << 5;
            ulonglong2 a0 = *(const ulonglong2*)(A0 + d);
            ulonglong2 a1 = *(const ulonglong2*)(A0 + Dm + d);
            ulonglong2 a2 = *(const ulonglong2*)(A0 + 2 * Dm + d);
            ulonglong2 a3 = *(const ulonglong2*)(A0 + 3 * Dm + d);
            #pragma unroll
            for (int r = 0; r < RPB; ++r) {
                ulonglong2 xp = *(const ulonglong2*)&xs[r * Dm + dbase + d];
                fma2(acc[r][0], xp.x, a0.x); fma2(acc[r][0], xp.y, a0.y);
                fma2(acc[r][1], xp.x, a1.x); fma2(acc[r][1], xp.y, a1.y);
                fma2(acc[r][2], xp.x, a2.x); fma2(acc[r][2], xp.y, a2.y);
                fma2(acc[r][3], xp.x, a3.x); fma2(acc[r][3], xp.y, a3.y);
            }
        }
        #pragma unroll
        for (int r = 0; r < RPB; ++r) {
            #pragma unroll
            for (int q = 0; q < 4; ++q) {
                float2 p = unpack2(acc[r][q]);
                float s = p.x + p.y;
                s += __shfl_xor_sync(0xffffffffu, s, 1);
                s += __shfl_xor_sync(0xffffffffu, s, 2);
                s += __shfl_xor_sync(0xffffffffu, s, 4);
                if (dpos == 0) sp2[h][r * 128 + c0 + q] = s;
            }
        }
    }
    __syncthreads();

    float thr = thr_p[0];
    float b2v = b2p[0];

    // ---- filter + polynomial score: threads 0..255 own (r,k) pairs
    if (t < RPB * 64) {
        int r = t >> 6, k = t & 63;
        int c = (row0 + r) & 511;
        float re = sp2[0][r * 128 + k]      + sp2[1][r * 128 + k];
        float im = sp2[0][r * 128 + 64 + k] + sp2[1][r * 128 + 64 + k];
        float gr = Gr[c * Kk + k], gi = Gi[c * Kk + k];
        float lr = Lr[c * Kk + k], li = Li[c * Kk + k];
        float pw = fmaf(re, re, im * im);
        float fg = fmaf(re, gr, -im * gi);
        float fl = fmaf(re, lr, -im * li);
        float fr = (pw > thr) ? (fg + fl) : fg;
        float s = ac[10 * Kk + k];
        #pragma unroll
        for (int j = 9; j >= 0; --j) s = fmaf(s, fr, ac[j * Kk + k]);
        s += b2v;
        sp2[0][r * 128 + k]      = s;    // score
        sp2[0][r * 128 + 64 + k] = fr;   // fr
    }
    __syncthreads();

    // ---- softmax per row (warps 0..3), write duplicated (a,a) pairs
    if (w < RPB) {
        float s0 = sp2[0][w * 128 + lane],      s1 = sp2[0][w * 128 + 32 + lane];
        float f0 = sp2[0][w * 128 + 64 + lane], f1 = sp2[0][w * 128 + 96 + lane];
        float mx = fmaxf(s0, s1);
        #pragma unroll
        for (int off = 16; off; off >>= 1)
            mx = fmaxf(mx, __shfl_xor_sync(0xffffffffu, mx, off));
        float e0 = __expf(s0 - mx), e1 = __expf(s1 - mx);
        float sm = e0 + e1;
        #pragma unroll
        for (int off = 16; off; off >>= 1)
            sm += __shfl_xor_sync(0xffffffffu, sm, off);
        float inv = 1.0f / sm;
        float a0 = e0 * inv * f0;
        float a1 = e1 * inv * f1;
        int i0 = lane * (RPB * 2) + w * 2;
        int i1 = (32 + lane) * (RPB * 2) + w * 2;
        as2[i0] = a0; as2[i0 + 1] = a0;
        as2[i1] = a1; as2[i1 + 1] = a1;
    }
    __syncthreads();

    // ---- pooled (f32x2 packed FMA) + LN in registers
    {
        int d0 = t * 2;
        ull acc[RPB];
        #pragma unroll
        for (int r = 0; r < RPB; ++r)
            acc[r] = *(const ull*)&xs[r * Dm + d0];
        #pragma unroll 4
        for (int k = 0; k < 64; ++k) {
            ull ev = *(const ull*)&E[k * Dm + d0];
            const ulonglong2* aw = (const ulonglong2*)&as2[k * (RPB * 2)];
            ulonglong2 aw01 = aw[0];
            ulonglong2 aw23 = aw[1];
            fma2(acc[0], ev, aw01.x);
            fma2(acc[1], ev, aw01.y);
            fma2(acc[2], ev, aw23.x);
            fma2(acc[3], ev, aw23.y);
        }
        float2 v[RPB];
        #pragma unroll
        for (int r = 0; r < RPB; ++r) {
            v[r] = unpack2(acc[r]);
            float a = v[r].x + v[r].y;
            float b = fmaf(v[r].x, v[r].x, v[r].y * v[r].y);
            #pragma unroll
            for (int off = 16; off; off >>= 1) {
                a += __shfl_xor_sync(0xffffffffu, a, off);
                b += __shfl_xor_sync(0xffffffffu, b, off);
            }
            if (lane == 0) { red1[r][w] = a; red2[r][w] = b; }
        }
        __syncthreads();
        if (t < RPB) {
            float s1 = 0.f, s2 = 0.f;
            #pragma unroll
            for (int i = 0; i < 16; ++i) { s1 += red1[t][i]; s2 += red2[t][i]; }
            float mean = s1 * (1.0f / 1024.0f);
            float var = fmaf(-mean, mean, s2 * (1.0f / 1024.0f));
            rmean[t] = mean;
            rrstd[t] = rsqrtf(var + 1e-5f);
        }
        __syncthreads();

        float2 g2 = *(const float2*)&gamma[d0];
        float2 b2g = *(const float2*)&beta[d0];
        #pragma unroll
        for (int r = 0; r < RPB; ++r) {
            float mu = rmean[r], rs = rrstd[r];
            float2 o;
            o.x = fmaf((v[r].x - mu) * rs, g2.x, b2g.x);
            o.y = fmaf((v[r].y - mu) * rs, g2.y, b2g.y);
            *(float2*)&out[(row0 + r) * Dm + d0] = o;
        }
    }
}

// ---------------------------------------------------------------------------
extern "C" void kernel_launch(void* const* d_in, const int* in_sizes, int n_in,
                              void* d_out, int out_size) {
    const float* tokens = (const float*)d_in[0];
    const float* thresh = (const float*)d_in[1];
    const float* P      = (const float*)d_in[2];
    const float* Gr     = (const float*)d_in[3];
    const float* Gi     = (const float*)d_in[4];
    const float* Lr     = (const float*)d_in[5];
    const float* Li     = (const float*)d_in[6];
    const float* E      = (const float*)d_in[7];
    const float* W1     = (const float*)d_in[8];
    const float* b1     = (const float*)d_in[9];
    const float* w2     = (const float*)d_in[10];
    const float* b2     = (const float*)d_in[11];
    const float* gamma  = (const float*)d_in[12];
    const float* beta   = (const float*)d_in[13];
    float* out = (float*)d_out;

    k_pre<<<256, 256>>>(P, E, W1);
    k_powred<<<64, 256>>>(b1, w2);
    k_main<<<NROWS / RPB, 512>>>(tokens, thresh, Gr, Gi, Lr, Li, E,
                                 b2, gamma, beta, out);
}

// round 17
// speedup vs baseline: 1.2624x; 1.0926x over previous
#include <cuda_runtime.h>
#include <cuda_bf16.h>

// ---------------------------------------------------------------------------
// AdaptiveSpectralBlock: B=2, C=512, D=1024, K=64, FB=513
//   spectrum = tokens @ A; DFT symmetry: Are[1024-d]=Are[d], Aim[1024-d]=-Aim[d]
//   => A built only for d=0..512; spectrum folded to K=512 (xsp/xsm).
//   fr = Re(spectrum*gw + spectrum*mask*lw)
//   score[k](t=fr) = b2 + sum_j t^j * Acoef[j][k]   (exact-GELU Taylor moments)
//   weights = softmax_k(score); pooled = (weights*fr) @ E; out = LN(tokens+pooled)
// ---------------------------------------------------------------------------

#define Dm 1024
#define Kk 64
#define FB 513
#define NROWS 1024            // B*C
#define RPB 4                 // rows per k_main block
#define NJ 11                 // poly degree 0..10
#define NSPLIT 8              // j-splits in E@W1 GEMM

typedef unsigned long long ull;

// scratch (allocation-free rule: __device__ globals)
__device__ float g_AT[128 * Dm];                // [col][d]; cols 0..63 re, 64..127 im; d 0..512 used
__device__ float g_Mpart2[NSPLIT * Kk * Dm];    // partial m[k][d] per j-split
__device__ float g_Acoef[NJ * Kk];              // [j][k]

// gelu(y) = 0.5y + (1/sqrt(2pi)) (y^2 - y^4/6 + y^6/40 - y^8/336 + y^10/3456)
__constant__ float c_cp[NJ] = {
    0.0f, 0.5f,
    0.39894228040143270f, 0.0f,
   -0.06649038006690545f, 0.0f,
    0.00997355701003582f, 0.0f,
   -0.00118732821548045f, 0.0f,
    1.1543006956058354e-4f
};
__constant__ float c_binom[NJ][NJ] = {
    {1,0,0,0,0,0,0,0,0,0,0},
    {1,1,0,0,0,0,0,0,0,0,0},
    {1,2,1,0,0,0,0,0,0,0,0},
    {1,3,3,1,0,0,0,0,0,0,0},
    {1,4,6,4,1,0,0,0,0,0,0},
    {1,5,10,10,5,1,0,0,0,0,0},
    {1,6,15,20,15,6,1,0,0,0,0},
    {1,7,21,35,35,21,7,1,0,0,0},
    {1,8,28,56,70,56,28,8,1,0,0},
    {1,9,36,84,126,126,84,36,9,1,0},
    {1,10,45,120,210,252,210,120,45,10,1}
};

__device__ __forceinline__ void fma2(ull& acc, ull a, ull b) {
    asm("fma.rn.f32x2 %0, %1, %2, %0;" : "+l"(acc) : "l"(a), "l"(b));
}
__device__ __forceinline__ ull dup2(float v) {
    ull r;
    asm("mov.b64 %0, {%1, %1};" : "=l"(r) : "f"(v));
    return r;
}
__device__ __forceinline__ float2 unpack2(ull v) {
    float2 r;
    asm("mov.b64 {%0, %1}, %2;" : "=f"(r.x), "=f"(r.y) : "l"(v));
    return r;
}

// ---------------------------------------------------------------------------
// K_pre: fused precompute.
//   blocks [0,64):    buildA for d-group of 8 within d=0..511; block 0 also
//                     accumulates column d=512 (alternating sum) for free.
//   blocks [64,192):  m = E @ W1 split-K GEMM partials
// ---------------------------------------------------------------------------
__global__ void __launch_bounds__(256) k_pre(const float* __restrict__ P,
                                             const float* __restrict__ E,
                                             const float* __restrict__ W1) {
    __shared__ __align__(16) char sm[40960];
    int t = threadIdx.x;

    if (blockIdx.x < 64) {
        // ---------------- buildA role ----------------
        float2* tw = (float2*)sm;                  // 8KB: [ff][dd] (cos,-sin), 128x8
        float*  sP = (float*)(sm + 8192);          // 32KB P f-tile (128 f x 64 k)

        int k = t & 63, rep = t >> 6;              // rep = f-quarter within tile
        int d0 = blockIdx.x * 8;                   // 0..504

        ull acc[8];
        #pragma unroll
        for (int q = 0; q < 8; ++q) acc[q] = 0ull;
        float acc512 = 0.f;                        // sum (-1)^f * P[f][k] (rep slice)

        const float4* P4 = (const float4*)P;
        for (int f0 = 0; f0 < 512; f0 += 128) {
            __syncthreads();                       // protect smem reuse
            #pragma unroll
            for (int i = 0; i < 8; ++i) {
                int lin4 = t + i * 256;            // 2048 float4 = 128 f x 16
                ((float4*)sP)[lin4] = P4[f0 * 16 + lin4];
            }
            // trig tile: 1024 float2 (128 ff x 8 dd). f*d < 2^19 -> exact args.
            #pragma unroll
            for (int i = 0; i < 4; ++i) {
                int lin = t + i * 256;
                int ff = lin >> 3, dd = lin & 7;
                float arg = (float)((f0 + ff) * (d0 + dd)) * (1.0f / 512.0f);
                float s, c;
                sincospif(arg, &s, &c);
                tw[lin] = make_float2(c, -s);
            }
            __syncthreads();
            int base = rep << 5;                   // this rep's 32-ff slice
            #pragma unroll 8
            for (int f2 = 0; f2 < 32; ++f2) {
                int ff = base + f2;
                float pv = sP[ff * 64 + k];
                ull pvd = dup2(pv);
                const ulonglong2* twp = (const ulonglong2*)&tw[ff * 8];
                ulonglong2 w01 = twp[0];
                ulonglong2 w23 = twp[1];
                fma2(acc[0], w01.x, pvd); fma2(acc[1], w01.y, pvd);
                fma2(acc[2], w23.x, pvd); fma2(acc[3], w23.y, pvd);
                ulonglong2 w45 = twp[2];
                ulonglong2 w67 = twp[3];
                fma2(acc[4], w45.x, pvd); fma2(acc[5], w45.y, pvd);
                fma2(acc[6], w67.x, pvd); fma2(acc[7], w67.y, pvd);
                // d=512 column: (-1)^f (base even -> parity of f2)
                acc512 = fmaf((f2 & 1) ? -1.f : 1.f, pv, acc512);
            }
        }
        // in-block combine of the 4 rep partials (deterministic order)
        __syncthreads();
        float2* st = (float2*)(sm + 8192);         // 16KB: [rep][k][dd]
        float* s512 = (float*)(sm + 8192 + 16384); // 1KB: [rep][k]
        #pragma unroll
        for (int q = 0; q < 8; ++q)
            st[((rep << 6) + k) * 8 + q] = unpack2(acc[q]);
        s512[rep * 64 + k] = acc512;
        __syncthreads();
        #pragma unroll
        for (int i = 0; i < 2; ++i) {
            int p = t + i * 256;                   // 0..511 = (k, dd)
            int kk = p >> 3, dd = p & 7;
            float2 s0 = st[((0 << 6) + kk) * 8 + dd];
            float2 s1 = st[((1 << 6) + kk) * 8 + dd];
            float2 s2 = st[((2 << 6) + kk) * 8 + dd];
            float2 s3 = st[((3 << 6) + kk) * 8 + dd];
            float re = (s0.x + s1.x) + (s2.x + s3.x);
            float im = (s0.y + s1.y) + (s2.y + s3.y);
            int d = d0 + dd;
            // Nyquist bin f=512: angle = pi*d -> cos = (-1)^d, sin = 0
            float pn = P[512 * 64 + kk];
            re = fmaf((d & 1) ? -1.f : 1.f, pn, re);
            g_AT[kk * Dm + d]        = re;
            g_AT[(64 + kk) * Dm + d] = im;
        }
        // block 0 writes column d=512: re = sum reps + Nyquist (+P[512][k]); im = 0
        if (blockIdx.x == 0 && t < 64) {
            float r512 = (s512[0 * 64 + t] + s512[1 * 64 + t])
                       + (s512[2 * 64 + t] + s512[3 * 64 + t]);
            r512 += P[512 * 64 + t];               // f=512,d=512: cos(512*pi)=+1
            g_AT[t * Dm + 512]        = r512;
            g_AT[(64 + t) * Dm + 512] = 0.f;
        }
    } else {
        // ---------------- gemm role ----------------
        float* sE = (float*)sm;                    // 64x36 (9216B)
        float* sW = (float*)(sm + 9216);           // 32x64 (8192B)
        int bid = blockIdx.x - 64;
        int bd = bid & 15, bj = bid >> 4;
        int d0 = bd * 64, j0 = bj * 128;
        int tk = (t >> 4) * 4;
        int tc = t & 15;
        int td = tc * 4;

        ull acc[4][2];
        #pragma unroll
        for (int r = 0; r < 4; ++r) { acc[r][0] = 0ull; acc[r][1] = 0ull; }

        const float4* E4 = (const float4*)E;
        const float4* W14 = (const float4*)W1;

        for (int js = 0; js < 128; js += 32) {
            __syncthreads();
            #pragma unroll
            for (int i = 0; i < 2; ++i) {
                int lin4 = t + i * 256;
                int kr = lin4 >> 3, jc = lin4 & 7;
                float4 v = E4[kr * 256 + ((j0 + js) >> 2) + jc];
                *(float4*)&sE[kr * 36 + jc * 4] = v;
            }
            #pragma unroll
            for (int i = 0; i < 2; ++i) {
                int lin4 = t + i * 256;
                int jr = lin4 >> 4, dc = lin4 & 15;
                float4 v = W14[(j0 + js + jr) * 256 + (d0 >> 2) + dc];
                ((float4*)sW)[jr * 16 + dc] = v;
            }
            __syncthreads();
            #pragma unroll
            for (int jj = 0; jj < 32; ++jj) {
                ulonglong2 wp = ((const ulonglong2*)sW)[jj * 8 + tc];
                ull e0 = dup2(sE[(tk + 0) * 36 + jj]);
                ull e1 = dup2(sE[(tk + 1) * 36 + jj]);
                ull e2 = dup2(sE[(tk + 2) * 36 + jj]);
                ull e3 = dup2(sE[(tk + 3) * 36 + jj]);
                fma2(acc[0][0], e0, wp.x); fma2(acc[0][1], e0, wp.y);
                fma2(acc[1][0], e1, wp.x); fma2(acc[1][1], e1, wp.y);
                fma2(acc[2][0], e2, wp.x); fma2(acc[2][1], e2, wp.y);
                fma2(acc[3][0], e3, wp.x); fma2(acc[3][1], e3, wp.y);
            }
        }
        #pragma unroll
        for (int r = 0; r < 4; ++r) {
            ulonglong2 o; o.x = acc[r][0]; o.y = acc[r][1];
            *(ulonglong2*)&g_Mpart2[((bj << 6) + tk + r) * Dm + d0 + td] = o;
        }
    }
}

// ----------- K2: reduce partials -> m; moments Acoef[j][k] (WG inline)
__global__ void __launch_bounds__(256) k_powred(const float* __restrict__ b1,
                                                const float* __restrict__ w2) {
    __shared__ float red[8][NJ];
    int k = blockIdx.x, t = threadIdx.x;
    int d = t * 4;
    int w = t >> 5, lane = t & 31;

    float4 m4 = make_float4(0.f, 0.f, 0.f, 0.f);
    #pragma unroll
    for (int p = 0; p < NSPLIT; ++p) {
        float4 v = *(const float4*)&g_Mpart2[((p << 6) + k) * Dm + d];
        m4.x += v.x; m4.y += v.y; m4.z += v.z; m4.w += v.w;
    }
    float4 b4 = *(const float4*)&b1[d];
    float4 w4 = *(const float4*)&w2[d];

    float accj[NJ];
    #pragma unroll
    for (int j = 0; j < NJ; ++j) accj[j] = 0.f;

    float mlane[4] = {m4.x, m4.y, m4.z, m4.w};
    float blane[4] = {b4.x, b4.y, b4.z, b4.w};
    float wlane[4] = {w4.x, w4.y, w4.z, w4.w};
    #pragma unroll
    for (int q = 0; q < 4; ++q) {
        float bb = blane[q], ww = wlane[q], mm = mlane[q];
        float bp[NJ];
        bp[0] = 1.f;
        #pragma unroll
        for (int i = 1; i < NJ; ++i) bp[i] = bp[i - 1] * bb;
        float mp = 1.f;
        #pragma unroll
        for (int j = 0; j < NJ; ++j) {
            float gj = 0.f;
            #pragma unroll
            for (int p = 0; p < NJ; ++p) {
                if (p >= j) gj = fmaf(c_cp[p] * c_binom[p][j], bp[p - j], gj);
            }
            accj[j] = fmaf(ww * gj, mp, accj[j]);
            mp *= mm;
        }
    }
    #pragma unroll
    for (int j = 0; j < NJ; ++j) {
        float a = accj[j];
        #pragma unroll
        for (int off = 16; off; off >>= 1)
            a += __shfl_xor_sync(0xffffffffu, a, off);
        if (lane == 0) red[w][j] = a;
    }
    __syncthreads();
    if (t < NJ) {
        float s = 0.f;
        #pragma unroll
        for (int i = 0; i < 8; ++i) s += red[i][t];
        g_Acoef[t * Kk + k] = s;
    }
}

// ------------------------------------------------------- K3: fused main
// grid 256 blocks x 512 threads, 4 rows per block, 2 CTAs/SM.
// Spectrum folded via DFT symmetry: K=512 with xsp (re) / xsm (im).
__global__ void __launch_bounds__(512, 2) k_main(
    const float* __restrict__ tokens, const float* __restrict__ thr_p,
    const float* __restrict__ Gr, const float* __restrict__ Gi,
    const float* __restrict__ Lr, const float* __restrict__ Li,
    const float* __restrict__ E, const float* __restrict__ b2p,
    const float* __restrict__ gamma, const float* __restrict__ beta,
    float* __restrict__ out)
{
    __shared__ float xs[RPB * Dm];              // 16KB raw tokens
    __shared__ float xsp[RPB * 512];            // 8KB x[d]+x[1024-d] (xsp[0]=x[0])
    __shared__ float xsm[RPB * 512];            // 8KB x[d]-x[1024-d] (xsm[0]=0)
    __shared__ float spR[RPB * 64];             // spectrum re -> score
    __shared__ float spI[RPB * 64];             // spectrum im -> fr
    __shared__ float as2[Kk * RPB * 2];         // weight*fr dup pairs [k][r][2]
    __shared__ float ac[NJ * Kk];
    __shared__ float a512s[Kk];                 // Are[k][512]
    __shared__ float red1[RPB][16], red2[RPB][16];
    __shared__ float rmean[RPB], rrstd[RPB];

    int t = threadIdx.x;
    int row0 = blockIdx.x * RPB;
    int w = t >> 5, lane = t & 31;

    // ---- stage tokens + coefficients
    {
        const float4* tok4 = (const float4*)(tokens + row0 * Dm);
        float4* xs4 = (float4*)xs;
        #pragma unroll
        for (int i = 0; i < 2; ++i) xs4[t + i * 512] = tok4[t + i * 512];
        for (int i = t; i < NJ * Kk; i += 512) ac[i] = g_Acoef[i];
        if (t < Kk) a512s[t] = g_AT[t * Dm + 512];
    }
    __syncthreads();

    // ---- fold: xsp/xsm
    #pragma unroll
    for (int i = 0; i < 4; ++i) {
        int lin = t + i * 512;                  // 0..2047
        int r = lin >> 9, d = lin & 511;
        float a = xs[r * Dm + d];
        if (d == 0) {
            xsp[r * 512] = a;
            xsm[r * 512] = 0.f;
        } else {
            float b = xs[r * Dm + 1024 - d];
            xsp[r * 512 + d] = a + b;
            xsm[r * 512 + d] = a - b;
        }
    }
    __syncthreads();

    // ---- spectrum (folded): warps 0..7 -> re over xsp, 8..15 -> im over xsm.
    //      lane: cg2 = lane>>3 picks col pair, dpos = lane&7 8-way depth split.
    {
        int h2 = w >> 3;                        // 0=re, 1=im
        int cw = w & 7;
        int cg2 = lane >> 3, dpos = lane & 7;
        int c = cw * 8 + cg2 * 2;               // col within 64 (pair c, c+1)
        const float* Ac0 = g_AT + (h2 * 64 + c) * Dm;
        const float* Ac1 = Ac0 + Dm;
        const float* src = h2 ? xsm : xsp;

        ull acc[RPB][2];
        #pragma unroll
        for (int r = 0; r < RPB; ++r) { acc[r][0] = 0ull; acc[r][1] = 0ull; }

        int dbase = dpos << 2;
        #pragma unroll 4
        for (int it = 0; it < 16; ++it) {
            int d = dbase + (it << 5);
            ulonglong2 a0 = *(const ulonglong2*)(Ac0 + d);
            ulonglong2 a1 = *(const ulonglong2*)(Ac1 + d);
            #pragma unroll
            for (int r = 0; r < RPB; ++r) {
                ulonglong2 xp = *(const ulonglong2*)&src[r * 512 + d];
                fma2(acc[r][0], xp.x, a0.x); fma2(acc[r][0], xp.y, a0.y);
                fma2(acc[r][1], xp.x, a1.x); fma2(acc[r][1], xp.y, a1.y);
            }
        }
        float* dst = h2 ? spI : spR;
        #pragma unroll
        for (int r = 0; r < RPB; ++r) {
            #pragma unroll
            for (int q = 0; q < 2; ++q) {
                float2 p = unpack2(acc[r][q]);
                float s = p.x + p.y;
                s += __shfl_xor_sync(0xffffffffu, s, 1);
                s += __shfl_xor_sync(0xffffffffu, s, 2);
                s += __shfl_xor_sync(0xffffffffu, s, 4);
                if (dpos == 0) dst[r * 64 + c + q] = s;
            }
        }
    }
    __syncthreads();

    float thr = thr_p[0];
    float b2v = b2p[0];

    // ---- filter + polynomial score: threads 0..255 own (r,k) pairs
    if (t < RPB * 64) {
        int r = t >> 6, k = t & 63;
        int c = (row0 + r) & 511;
        float re = fmaf(xs[r * Dm + 512], a512s[k], spR[r * 64 + k]);
        float im = spI[r * 64 + k];
        float gr = Gr[c * Kk + k], gi = Gi[c * Kk + k];
        float lr = Lr[c * Kk + k], li = Li[c * Kk + k];
        float pw = fmaf(re, re, im * im);
        float fg = fmaf(re, gr, -im * gi);
        float fl = fmaf(re, lr, -im * li);
        float fr = (pw > thr) ? (fg + fl) : fg;
        float s = ac[10 * Kk + k];
        #pragma unroll
        for (int j = 9; j >= 0; --j) s = fmaf(s, fr, ac[j * Kk + k]);
        s += b2v;
        spR[r * 64 + k] = s;        // score
        spI[r * 64 + k] = fr;       // fr
    }
    __syncthreads();

    // ---- softmax per row (warps 0..3), write duplicated (a,a) pairs
    if (w < RPB) {
        float s0 = spR[w * 64 + lane], s1 = spR[w * 64 + 32 + lane];
        float f0 = spI[w * 64 + lane], f1 = spI[w * 64 + 32 + lane];
        float mx = fmaxf(s0, s1);
        #pragma unroll
        for (int off = 16; off; off >>= 1)
            mx = fmaxf(mx, __shfl_xor_sync(0xffffffffu, mx, off));
        float e0 = __expf(s0 - mx), e1 = __expf(s1 - mx);
        float sm = e0 + e1;
        #pragma unroll
        for (int off = 16; off; off >>= 1)
            sm += __shfl_xor_sync(0xffffffffu, sm, off);
        float inv = 1.0f / sm;
        float a0 = e0 * inv * f0;
        float a1 = e1 * inv * f1;
        int i0 = lane * (RPB * 2) + w * 2;
        int i1 = (32 + lane) * (RPB * 2) + w * 2;
        as2[i0] = a0; as2[i0 + 1] = a0;
        as2[i1] = a1; as2[i1 + 1] = a1;
    }
    __syncthreads();

    // ---- pooled (f32x2 packed FMA) + LN in registers
    {
        int d0 = t * 2;
        ull acc[RPB];
        #pragma unroll
        for (int r = 0; r < RPB; ++r)
            acc[r] = *(const ull*)&xs[r * Dm + d0];
        #pragma unroll 4
        for (int k = 0; k < 64; ++k) {
            ull ev = *(const ull*)&E[k * Dm + d0];
            const ulonglong2* aw = (const ulonglong2*)&as2[k * (RPB * 2)];
            ulonglong2 aw01 = aw[0];
            ulonglong2 aw23 = aw[1];
            fma2(acc[0], ev, aw01.x);
            fma2(acc[1], ev, aw01.y);
            fma2(acc[2], ev, aw23.x);
            fma2(acc[3], ev, aw23.y);
        }
        float2 v[RPB];
        #pragma unroll
        for (int r = 0; r < RPB; ++r) {
            v[r] = unpack2(acc[r]);
            float a = v[r].x + v[r].y;
            float b = fmaf(v[r].x, v[r].x, v[r].y * v[r].y);
            #pragma unroll
            for (int off = 16; off; off >>= 1) {
                a += __shfl_xor_sync(0xffffffffu, a, off);
                b += __shfl_xor_sync(0xffffffffu, b, off);
            }
            if (lane == 0) { red1[r][w] = a; red2[r][w] = b; }
        }
        __syncthreads();
        if (t < RPB) {
            float s1 = 0.f, s2 = 0.f;
            #pragma unroll
            for (int i = 0; i < 16; ++i) { s1 += red1[t][i]; s2 += red2[t][i]; }
            float mean = s1 * (1.0f / 1024.0f);
            float var = fmaf(-mean, mean, s2 * (1.0f / 1024.0f));
            rmean[t] = mean;
            rrstd[t] = rsqrtf(var + 1e-5f);
        }
        __syncthreads();

        float2 g2 = *(const float2*)&gamma[d0];
        float2 b2g = *(const float2*)&beta[d0];
        #pragma unroll
        for (int r = 0; r < RPB; ++r) {
            float mu = rmean[r], rs = rrstd[r];
            float2 o;
            o.x = fmaf((v[r].x - mu) * rs, g2.x, b2g.x);
            o.y = fmaf((v[r].y - mu) * rs, g2.y, b2g.y);
            *(float2*)&out[(row0 + r) * Dm + d0] = o;
        }
    }
}

// ---------------------------------------------------------------------------
extern "C" void kernel_launch(void* const* d_in, const int* in_sizes, int n_in,
                              void* d_out, int out_size) {
    const float* tokens = (const float*)d_in[0];
    const float* thresh = (const float*)d_in[1];
    const float* P      = (const float*)d_in[2];
    const float* Gr     = (const float*)d_in[3];
    const float* Gi     = (const float*)d_in[4];
    const float* Lr     = (const float*)d_in[5];
    const float* Li     = (const float*)d_in[6];
    const float* E      = (const float*)d_in[7];
    const float* W1     = (const float*)d_in[8];
    const float* b1     = (const float*)d_in[9];
    const float* w2     = (const float*)d_in[10];
    const float* b2     = (const float*)d_in[11];
    const float* gamma  = (const float*)d_in[12];
    const float* beta   = (const float*)d_in[13];
    float* out = (float*)d_out;

    k_pre<<<192, 256>>>(P, E, W1);
    k_powred<<<64, 256>>>(b1, w2);
    k_main<<<NROWS / RPB, 512>>>(tokens, thresh, Gr, Gi, Lr, Li, E,
                                 b2, gamma, beta, out);
}